// round 9
// baseline (speedup 1.0000x reference)
#include <cuda_runtime.h>
#include <cuda_fp16.h>
#include <cstdint>

// ---------------- problem constants ----------------
#define NS      1024
#define NV      99
#define ROWS    (NS*NV)       // 101376
#define INCH    64
#define MH      512
#define SH      512
#define KCAT    (INCH+MH)     // 576
#define SCALE0  30.0f

// ---------------- device scratch ----------------
__device__ float  g_wmod0[MH*INCH];
__device__ float  g_wmod1[MH*KCAT];
__device__ float  g_wmod2[MH*KCAT];
__device__ __half g_hW1[SH*SH];
__device__ __half g_hW2[SH*SH];
__device__ float  g_wdec[3*SH];
__device__ float  g_s0[NV*SH];
__device__ float  g_M0[NS*MH];
__device__ float  g_M1[NS*MH];
__device__ float  g_M2[NS*MH];
__device__ float  g_Z0[NS*KCAT];
__device__ float  g_Z1[NS*KCAT];
__device__ float  g_Xr[NS*INCH];
__device__ float  g_dir[(size_t)ROWS*3];

__device__ __forceinline__ float rna_tf32(float x){
    float y; asm("cvt.rna.tf32.f32 %0, %1;" : "=f"(y) : "f"(x)); return y;
}
__device__ __forceinline__ void cp16(uint32_t s, const void* g){
    asm volatile("cp.async.cg.shared.global [%0], [%1], 16;" :: "r"(s), "l"(g));
}
__device__ __forceinline__ void ldsm4(uint32_t& r0, uint32_t& r1, uint32_t& r2, uint32_t& r3,
                                      uint32_t addr){
    asm volatile("ldmatrix.sync.aligned.m8n8.x4.shared.b16 {%0,%1,%2,%3}, [%4];"
                 : "=r"(r0), "=r"(r1), "=r"(r2), "=r"(r3) : "r"(addr));
}

// ================= prep: weight-norms + s0 + X rounding (one launch) ============
__global__ void prep_kernel(const float* __restrict__ mv0, const float* __restrict__ mg0,
                            const float* __restrict__ mv1, const float* __restrict__ mg1,
                            const float* __restrict__ mv2, const float* __restrict__ mg2,
                            const float* __restrict__ sv1, const float* __restrict__ sg1,
                            const float* __restrict__ sv2, const float* __restrict__ sg2,
                            const float* __restrict__ dv,  const float* __restrict__ dg,
                            const float* __restrict__ sv0, const float* __restrict__ sg0,
                            const float* __restrict__ sb0, const float* __restrict__ X)
{
    __shared__ float red[256];
    int b = blockIdx.x, tid = threadIdx.x;
    if (b < 2563) {
        const float* v; const float* g; int cols, r, mode; // 0=fp32,1=tf32,2=half
        float*  o32 = nullptr; __half* o16 = nullptr;
        if      (b < 512)  { v=mv0; g=mg0; o32=g_wmod0; cols=INCH; r=b;      mode=1; }
        else if (b < 1024) { v=mv1; g=mg1; o32=g_wmod1; cols=KCAT; r=b-512;  mode=1; }
        else if (b < 1536) { v=mv2; g=mg2; o32=g_wmod2; cols=KCAT; r=b-1024; mode=1; }
        else if (b < 2048) { v=sv1; g=sg1; o16=g_hW1;   cols=SH;   r=b-1536; mode=2; }
        else if (b < 2560) { v=sv2; g=sg2; o16=g_hW2;   cols=SH;   r=b-2048; mode=2; }
        else               { v=dv;  g=dg;  o32=g_wdec;  cols=SH;   r=b-2560; mode=0; }
        const float* vr = v + (size_t)r * cols;
        float ss = 0.f;
        for (int c = tid; c < cols; c += 256) { float x = vr[c]; ss += x * x; }
        red[tid] = ss; __syncthreads();
        for (int s = 128; s > 0; s >>= 1) {
            if (tid < s) red[tid] += red[tid + s];
            __syncthreads();
        }
        float scale = g[r] * rsqrtf(red[0]);
        for (int c = tid; c < cols; c += 256) {
            float w = vr[c] * scale;
            if (mode == 2)      o16[(size_t)r * cols + c] = __float2half(w);
            else if (mode == 1) o32[(size_t)r * cols + c] = rna_tf32(w);
            else                o32[(size_t)r * cols + c] = w;
        }
    } else if (b < 2662) {          // s0 table
        int p = b - 2563;
        float t = (float)p / 99.f;
        for (int j = tid; j < SH; j += 256) {
            float vv = sv0[j];
            float w  = sg0[j] * vv * rsqrtf(vv * vv);
            g_s0[p * SH + j] = sinf(SCALE0 * (t * w + sb0[j]));
        }
    } else {                        // X rounding + Z prefix
        int i0 = (b - 2662) * 256 + tid;
        for (int i = i0; i < NS * INCH; i += 64 * 256) {
            float v = rna_tf32(X[i]);
            int s = i >> 6, c = i & 63;
            g_Xr[i] = v;
            g_Z0[(size_t)s * KCAT + c] = v;
            g_Z1[(size_t)s * KCAT + c] = v;
        }
    }
}

// ================= mod GEMM (mma.sync tf32, silu, Z-writeback) — 64x128 tiles ====
#define BMM 64
#define BNM 128
#define BKM 32
#define SST 36
__global__ __launch_bounds__(256, 2)
void gemm_mod_kernel(const float* __restrict__ A, const float* __restrict__ W,
                     const float* __restrict__ bias, float* __restrict__ out,
                     float* __restrict__ zout, int K)
{
    extern __shared__ float sm[];
    float* sA = sm;
    float* sB = sm + 2 * BMM * SST;
    const int tid = threadIdx.x;
    const int rowBase = blockIdx.y * BMM;
    const int colBase = blockIdx.x * BNM;
    const uint32_t sA_u = (uint32_t)__cvta_generic_to_shared(sA);
    const uint32_t sB_u = (uint32_t)__cvta_generic_to_shared(sB);
    const int lane = tid & 31, warp = tid >> 5;
    const int wm = warp & 3, wn = warp >> 2;
    const int gg = lane >> 2, tt = lane & 3;
    float acc[8][4] = {};
    const int nk = K / BKM;

    auto load_stage = [&](int i, int buf){
        int k0 = i * BKM;
        #pragma unroll
        for (int it = 0; it < 2; it++){
            int c  = tid + it * 256;
            int r  = c >> 3;
            int kc = (c & 7) * 4;
            cp16(sA_u + (uint32_t)((buf * BMM * SST + r * SST + kc) * 4),
                 &A[(size_t)(rowBase + r) * K + k0 + kc]);
        }
        #pragma unroll
        for (int it = 0; it < 4; it++){
            int c  = tid + it * 256;
            int r  = c >> 3;
            int kc = (c & 7) * 4;
            cp16(sB_u + (uint32_t)((buf * BNM * SST + r * SST + kc) * 4),
                 &W[(size_t)(colBase + r) * K + k0 + kc]);
        }
        asm volatile("cp.async.commit_group;");
    };

    load_stage(0, 0);
    for (int i = 0; i < nk; i++){
        if (i + 1 < nk) { load_stage(i + 1, (i + 1) & 1); asm volatile("cp.async.wait_group 1;"); }
        else            { asm volatile("cp.async.wait_group 0;"); }
        __syncthreads();
        const float* cA = sA + (i & 1) * BMM * SST;
        const float* cB = sB + (i & 1) * BNM * SST;
        #pragma unroll
        for (int kk = 0; kk < BKM; kk += 8){
            uint32_t a[4], b[8][2];
            {
                int r = wm * 16 + gg;
                a[0] = __float_as_uint(cA[r * SST + kk + tt]);
                a[1] = __float_as_uint(cA[(r + 8) * SST + kk + tt]);
                a[2] = __float_as_uint(cA[r * SST + kk + tt + 4]);
                a[3] = __float_as_uint(cA[(r + 8) * SST + kk + tt + 4]);
            }
            #pragma unroll
            for (int ni = 0; ni < 8; ni++){
                int c = wn * 64 + ni * 8 + gg;
                b[ni][0] = __float_as_uint(cB[c * SST + kk + tt]);
                b[ni][1] = __float_as_uint(cB[c * SST + kk + tt + 4]);
            }
            #pragma unroll
            for (int ni = 0; ni < 8; ni++){
                float* d = acc[ni];
                asm volatile(
                    "mma.sync.aligned.m16n8k8.row.col.f32.tf32.tf32.f32 "
                    "{%0,%1,%2,%3}, {%4,%5,%6,%7}, {%8,%9}, {%0,%1,%2,%3};"
                    : "+f"(d[0]), "+f"(d[1]), "+f"(d[2]), "+f"(d[3])
                    : "r"(a[0]), "r"(a[1]), "r"(a[2]), "r"(a[3]),
                      "r"(b[ni][0]), "r"(b[ni][1]));
            }
        }
        __syncthreads();
    }

    int row0 = rowBase + wm * 16 + gg;
    #pragma unroll
    for (int ni = 0; ni < 8; ni++){
        int col = colBase + wn * 64 + ni * 8 + tt * 2;
        float b0 = bias[col], b1 = bias[col + 1];
        #pragma unroll
        for (int h = 0; h < 2; h++){
            int row = row0 + h * 8;
            float v0 = acc[ni][h * 2 + 0] + b0;
            float v1 = acc[ni][h * 2 + 1] + b1;
            v0 = v0 / (1.f + __expf(-v0));
            v1 = v1 / (1.f + __expf(-v1));
            *reinterpret_cast<float2*>(&out[(size_t)row * 512 + col]) = make_float2(v0, v1);
            if (zout)
                *reinterpret_cast<float2*>(&zout[(size_t)row * KCAT + 64 + col]) =
                    make_float2(rna_tf32(v0), rna_tf32(v1));
        }
    }
}

// ================= FUSED siren layers 1+2 + decoder (one kernel) ================
// Per CTA: 128 rows. Phase 1 (stages 0-31): H1 = (1-M1)*sin(H0 @ W1^T + b1) into
// SMEM fp16 tiles, with H0 = (1-M0)*s0 produced on the fly. Phase 2 (stages
// 32-63): layer2 = (1-M2)*sin(H1 @ W2^T + b2), immediately dotted with wdec in
// the epilogue; per-row 3-vector reduced in SMEM and stored to g_dir.
// SMEM map (from aligned base):
//   [0, 128K)        : H1 tiles, 8 x 16KB (k-tile major, ldmatrix swizzle)
//   [128K, 160K)     : A produce double buffer (2 x 16KB)
//   [160K, 192K)     : B cp.async double buffer (2 x 16KB)
//   [192K, +6K)      : wdec (3 x 512 f32)
//   [198K, +3K)      : per-row decoder reduction buffer (128 x 3 x 2 f32)
#define FUS_SMEM (131072 + 32768 + 32768 + 6144 + 3072 + 1024)

__global__ __launch_bounds__(256, 1)
void fused_siren_kernel(const __half* __restrict__ W1, const __half* __restrict__ W2,
                        const float* __restrict__ b1v, const float* __restrict__ b2v,
                        const float* __restrict__ M0p, const float* __restrict__ M1p,
                        const float* __restrict__ M2p)
{
    extern __shared__ __align__(1024) char smem_raw[];
    uint32_t base  = (uint32_t)__cvta_generic_to_shared(smem_raw);
    uint32_t abase = (base + 1023u) & ~1023u;
    const uint32_t H1b = abase;
    const uint32_t Ab  = abase + 131072;
    const uint32_t Bb  = abase + 163840;
    float* wds = reinterpret_cast<float*>(smem_raw + (abase - base) + 196608);
    float* redb = wds + 1536;

    const int tid = threadIdx.x, warp = tid >> 5, lane = tid & 31;
    const int rowBase = blockIdx.x * 128;
    const int wm = warp & 3, wn = warp >> 2;
    const int gl = (lane >> 3) & 1, gh = lane >> 4, lr = lane & 7;
    const int gg = lane >> 2, tt = lane & 3;

    for (int i = tid; i < 1536; i += 256) wds[i] = g_wdec[i];

    auto load_stage = [&](int g){
        int nc = (g >> 3) & 3, t = g & 7, buf = g & 1;
        if (g < 32){
            // produce A tile: half((1-M0)*s0), swizzled
            uint32_t aBuf = Ab + buf * 16384;
            int k0 = t * 64;
            #pragma unroll
            for (int it = 0; it < 4; it++){
                int idx = tid + it * 256;
                int r = idx >> 3, c = idx & 7;
                int row = rowBase + r;
                int strand = row / NV, p = row - strand * NV;
                const float4* m4 = reinterpret_cast<const float4*>(&M0p[(size_t)strand * MH + k0 + c * 8]);
                const float4* s4 = reinterpret_cast<const float4*>(&g_s0[p * SH + k0 + c * 8]);
                float4 m0 = m4[0], m1 = m4[1], s0v = s4[0], s1v = s4[1];
                __half2 h0 = __floats2half2_rn((1.f - m0.x) * s0v.x, (1.f - m0.y) * s0v.y);
                __half2 h1 = __floats2half2_rn((1.f - m0.z) * s0v.z, (1.f - m0.w) * s0v.w);
                __half2 h2 = __floats2half2_rn((1.f - m1.x) * s1v.x, (1.f - m1.y) * s1v.y);
                __half2 h3 = __floats2half2_rn((1.f - m1.z) * s1v.z, (1.f - m1.w) * s1v.w);
                uint32_t off = (uint32_t)(r * 128 + ((c ^ (r & 7)) * 16));
                asm volatile("st.shared.v4.b32 [%0], {%1,%2,%3,%4};"
                             :: "r"(aBuf + off),
                                "r"(*reinterpret_cast<uint32_t*>(&h0)),
                                "r"(*reinterpret_cast<uint32_t*>(&h1)),
                                "r"(*reinterpret_cast<uint32_t*>(&h2)),
                                "r"(*reinterpret_cast<uint32_t*>(&h3)) : "memory");
            }
        }
        const __half* W = (g < 32) ? W1 : W2;
        uint32_t bBuf = Bb + buf * 16384;
        int k0 = t * 64, colB = nc * 128;
        #pragma unroll
        for (int it = 0; it < 4; it++){
            int idx = tid + it * 256;
            int r = idx >> 3, c = idx & 7;
            uint32_t off = (uint32_t)(r * 128 + ((c ^ (r & 7)) * 16));
            cp16(bBuf + off, &W[(size_t)(colB + r) * 512 + k0 + c * 8]);
        }
        asm volatile("cp.async.commit_group;");
    };

    float acc[2][8][4] = {};
    float p3[4][3];
    #pragma unroll
    for (int q = 0; q < 4; q++){ p3[q][0] = 0.f; p3[q][1] = 0.f; p3[q][2] = 0.f; }

    load_stage(0);
    load_stage(1);

    for (int g = 0; g < 64; g++){
        if (g < 62) asm volatile("cp.async.wait_group 1;" ::: "memory");
        else        asm volatile("cp.async.wait_group 0;" ::: "memory");
        __syncthreads();
        int t = g & 7;
        uint32_t aBuf = (g < 32) ? (Ab + (g & 1) * 16384) : (H1b + t * 16384);
        uint32_t bBuf = Bb + (g & 1) * 16384;

        #pragma unroll
        for (int kk = 0; kk < 4; kk++){
            int kc = kk * 2 + gh;
            uint32_t a[2][4], b[4][4];
            #pragma unroll
            for (int mi = 0; mi < 2; mi++){
                int row = wm * 32 + mi * 16 + gl * 8 + lr;
                ldsm4(a[mi][0], a[mi][1], a[mi][2], a[mi][3],
                      aBuf + (uint32_t)(row * 128 + ((kc ^ lr) * 16)));
            }
            #pragma unroll
            for (int nq = 0; nq < 4; nq++){
                int nrow = wn * 64 + nq * 16 + gl * 8 + lr;
                ldsm4(b[nq][0], b[nq][1], b[nq][2], b[nq][3],
                      bBuf + (uint32_t)(nrow * 128 + ((kc ^ lr) * 16)));
            }
            #pragma unroll
            for (int mi = 0; mi < 2; mi++)
                #pragma unroll
                for (int nq = 0; nq < 4; nq++){
                    #pragma unroll
                    for (int hf = 0; hf < 2; hf++){
                        float* d = acc[mi][nq * 2 + hf];
                        asm volatile(
                            "mma.sync.aligned.m16n8k16.row.col.f32.f16.f16.f32 "
                            "{%0,%1,%2,%3}, {%4,%5,%6,%7}, {%8,%9}, {%0,%1,%2,%3};"
                            : "+f"(d[0]), "+f"(d[1]), "+f"(d[2]), "+f"(d[3])
                            : "r"(a[mi][0]), "r"(a[mi][1]), "r"(a[mi][2]), "r"(a[mi][3]),
                              "r"(b[nq][hf]), "r"(b[nq][2 + hf]));
                    }
                }
        }
        __syncthreads();
        if (g + 2 < 64) load_stage(g + 2);

        if (t == 7){
            int nc = (g >> 3) & 3;
            if (g < 32){
                // phase-1 epilogue: (1-M1)*sin(acc+b1) -> H1 tiles 2nc, 2nc+1
                #pragma unroll
                for (int mi = 0; mi < 2; mi++){
                    int rl0 = wm * 32 + mi * 16 + gg;
                    #pragma unroll
                    for (int ni = 0; ni < 8; ni++){
                        int colL = wn * 64 + ni * 8 + tt * 2;        // 0..127
                        int col  = nc * 128 + colL;
                        float bb0 = b1v[col], bb1 = b1v[col + 1];
                        int tile = nc * 2 + wn;
                        #pragma unroll
                        for (int h = 0; h < 2; h++){
                            int rl = rl0 + h * 8;
                            int row = rowBase + rl;
                            int strand = row / NV;
                            float g0 = 1.f - M1p[(size_t)strand * MH + col];
                            float g1 = 1.f - M1p[(size_t)strand * MH + col + 1];
                            float v0 = g0 * __sinf(acc[mi][ni][h * 2 + 0] + bb0);
                            float v1 = g1 * __sinf(acc[mi][ni][h * 2 + 1] + bb1);
                            __half2 hv = __floats2half2_rn(v0, v1);
                            uint32_t addr = H1b + tile * 16384
                                          + (uint32_t)(rl * 128 + ((ni ^ (rl & 7)) * 16) + tt * 4);
                            asm volatile("st.shared.b32 [%0], %1;"
                                         :: "r"(addr), "r"(*reinterpret_cast<uint32_t*>(&hv))
                                         : "memory");
                        }
                    }
                }
            } else {
                // phase-2 epilogue: decoder partials
                #pragma unroll
                for (int mi = 0; mi < 2; mi++){
                    int rl0 = wm * 32 + mi * 16 + gg;
                    #pragma unroll
                    for (int ni = 0; ni < 8; ni++){
                        int col = nc * 128 + wn * 64 + ni * 8 + tt * 2;
                        float bb0 = b2v[col], bb1 = b2v[col + 1];
                        #pragma unroll
                        for (int h = 0; h < 2; h++){
                            int rl = rl0 + h * 8;
                            int row = rowBase + rl;
                            int strand = row / NV;
                            float g0 = 1.f - M2p[(size_t)strand * MH + col];
                            float g1 = 1.f - M2p[(size_t)strand * MH + col + 1];
                            float v0 = g0 * __sinf(acc[mi][ni][h * 2 + 0] + bb0);
                            float v1 = g1 * __sinf(acc[mi][ni][h * 2 + 1] + bb1);
                            int q = mi * 2 + h;
                            #pragma unroll
                            for (int d = 0; d < 3; d++)
                                p3[q][d] += v0 * wds[d * 512 + col] + v1 * wds[d * 512 + col + 1];
                        }
                    }
                }
            }
            #pragma unroll
            for (int mi = 0; mi < 2; mi++)
                #pragma unroll
                for (int ni = 0; ni < 8; ni++)
                    #pragma unroll
                    for (int j = 0; j < 4; j++)
                        acc[mi][ni][j] = 0.f;
        }
    }

    // final decoder reduction: quad shfl, SMEM combine over wn, direct store
    #pragma unroll
    for (int q = 0; q < 4; q++)
        #pragma unroll
        for (int d = 0; d < 3; d++){
            float v = p3[q][d];
            v += __shfl_xor_sync(0xFFFFFFFFu, v, 1);
            v += __shfl_xor_sync(0xFFFFFFFFu, v, 2);
            p3[q][d] = v;
        }
    if (tt == 0){
        #pragma unroll
        for (int q = 0; q < 4; q++){
            int rl = wm * 32 + (q >> 1) * 16 + (q & 1) * 8 + gg;
            #pragma unroll
            for (int d = 0; d < 3; d++)
                redb[rl * 6 + d * 2 + wn] = p3[q][d];
        }
    }
    __syncthreads();
    if (tid < 128){
        int rl = tid;
        #pragma unroll
        for (int d = 0; d < 3; d++){
            float s = redb[rl * 6 + d * 2] + redb[rl * 6 + d * 2 + 1];
            g_dir[(size_t)(rowBase + rl) * 3 + d] = s * 0.01f;
        }
    }
}

// ================= cumsum (adds decoder bias per step) =================
__global__ void cumsum_kernel(float* __restrict__ out, const float* __restrict__ bd)
{
    int idx = blockIdx.x * blockDim.x + threadIdx.x;
    if (idx >= NS * 3) return;
    int s = idx / 3, d = idx - s * 3;
    float bias = bd[d] * 0.01f;
    float acc = 0.f;
    out[(size_t)s * 300 + d] = 0.f;
    for (int p = 0; p < NV; p++) {
        acc += g_dir[((size_t)s * NV + p) * 3 + d] + bias;
        out[(size_t)s * 300 + (size_t)(p + 1) * 3 + d] = acc;
    }
}

// ================= host launch =================
static void* sym(const void* s) { void* p = nullptr; cudaGetSymbolAddress(&p, s); return p; }

extern "C" void kernel_launch(void* const* d_in, const int* in_sizes, int n_in,
                              void* d_out, int out_size)
{
    const float* X   = (const float*)d_in[0];
    const float* mv0 = (const float*)d_in[1];  const float* mg0 = (const float*)d_in[2];  const float* mb0 = (const float*)d_in[3];
    const float* mv1 = (const float*)d_in[4];  const float* mg1 = (const float*)d_in[5];  const float* mb1 = (const float*)d_in[6];
    const float* mv2 = (const float*)d_in[7];  const float* mg2 = (const float*)d_in[8];  const float* mb2 = (const float*)d_in[9];
    const float* sv0 = (const float*)d_in[10]; const float* sg0 = (const float*)d_in[11]; const float* sb0 = (const float*)d_in[12];
    const float* sv1 = (const float*)d_in[13]; const float* sg1 = (const float*)d_in[14]; const float* sb1 = (const float*)d_in[15];
    const float* sv2 = (const float*)d_in[16]; const float* sg2 = (const float*)d_in[17]; const float* sb2 = (const float*)d_in[18];
    const float* dv  = (const float*)d_in[19]; const float* dg  = (const float*)d_in[20]; const float* db  = (const float*)d_in[21];
    float* out = (float*)d_out;

    float*  wmod0 = (float*)sym(g_wmod0);
    float*  wmod1 = (float*)sym(g_wmod1);
    float*  wmod2 = (float*)sym(g_wmod2);
    __half* hW1   = (__half*)sym(g_hW1);
    __half* hW2   = (__half*)sym(g_hW2);
    float*  M0    = (float*)sym(g_M0);
    float*  M1    = (float*)sym(g_M1);
    float*  M2    = (float*)sym(g_M2);
    float*  Z0    = (float*)sym(g_Z0);
    float*  Z1    = (float*)sym(g_Z1);
    float*  Xr    = (float*)sym(g_Xr);

    const int mod_smem = 2 * (BMM + BNM) * SST * 4;   // 55296
    static int attr_done = 0;
    if (!attr_done) {
        cudaFuncSetAttribute(gemm_mod_kernel, cudaFuncAttributeMaxDynamicSharedMemorySize, mod_smem);
        cudaFuncSetAttribute(fused_siren_kernel, cudaFuncAttributeMaxDynamicSharedMemorySize, FUS_SMEM);
        attr_done = 1;
    }

    // prep (launch 0)
    prep_kernel<<<2726, 256>>>(mv0, mg0, mv1, mg1, mv2, mg2, sv1, sg1, sv2, sg2,
                               dv, dg, sv0, sg0, sb0, X);

    // modulation chain (launches 1-3)
    {
        dim3 grid(512 / BNM, NS / BMM);
        gemm_mod_kernel<<<grid, 256, mod_smem>>>(Xr, wmod0, mb0, M0, Z0, INCH);
        gemm_mod_kernel<<<grid, 256, mod_smem>>>(Z0, wmod1, mb1, M1, Z1, KCAT);
        gemm_mod_kernel<<<grid, 256, mod_smem>>>(Z1, wmod2, mb2, M2, nullptr, KCAT);
    }

    // fused siren layers 1+2 + decoder (launch 4)
    fused_siren_kernel<<<ROWS / 128, 256, FUS_SMEM>>>(hW1, hW2, sb1, sb2, M0, M1, M2);

    // cumsum (launch 5)
    cumsum_kernel<<<(NS * 3 + 255) / 256, 256>>>(out, db);
    (void)in_sizes; (void)n_in; (void)out_size;
}

// round 10
// speedup vs baseline: 1.2888x; 1.2888x over previous
#include <cuda_runtime.h>
#include <cuda_fp16.h>
#include <cstdint>

// ---------------- problem constants ----------------
#define NS      1024
#define NV      99
#define ROWS    (NS*NV)       // 101376
#define INCH    64
#define MH      512
#define SH      512
#define KCAT    (INCH+MH)     // 576
#define SCALE0  30.0f

// ---------------- device scratch ----------------
__device__ float  g_wmod0[MH*INCH];
__device__ float  g_wmod1[MH*KCAT];
__device__ float  g_wmod2[MH*KCAT];
__device__ __half g_hW1[SH*SH];
__device__ __half g_hW2[SH*SH];
__device__ float  g_wdec[3*SH];
__device__ float  g_s0[NV*SH];
__device__ float  g_M0[NS*MH];
__device__ float  g_M1[NS*MH];
__device__ float  g_M2[NS*MH];
__device__ float  g_Z0[NS*KCAT];
__device__ float  g_Z1[NS*KCAT];
__device__ float  g_Xr[NS*INCH];
__device__ __half g_hHB[(size_t)ROWS*SH];
__device__ float  g_dir[(size_t)ROWS*3];

__device__ __forceinline__ float rna_tf32(float x){
    float y; asm("cvt.rna.tf32.f32 %0, %1;" : "=f"(y) : "f"(x)); return y;
}
__device__ __forceinline__ void cp16(uint32_t s, const void* g){
    asm volatile("cp.async.cg.shared.global [%0], [%1], 16;" :: "r"(s), "l"(g));
}
__device__ __forceinline__ void ldsm4(uint32_t& r0, uint32_t& r1, uint32_t& r2, uint32_t& r3,
                                      uint32_t addr){
    asm volatile("ldmatrix.sync.aligned.m8n8.x4.shared.b16 {%0,%1,%2,%3}, [%4];"
                 : "=r"(r0), "=r"(r1), "=r"(r2), "=r"(r3) : "r"(addr));
}

// ================= prep: weight-norms + s0 + X rounding (one launch) ============
__global__ void prep_kernel(const float* __restrict__ mv0, const float* __restrict__ mg0,
                            const float* __restrict__ mv1, const float* __restrict__ mg1,
                            const float* __restrict__ mv2, const float* __restrict__ mg2,
                            const float* __restrict__ sv1, const float* __restrict__ sg1,
                            const float* __restrict__ sv2, const float* __restrict__ sg2,
                            const float* __restrict__ dv,  const float* __restrict__ dg,
                            const float* __restrict__ sv0, const float* __restrict__ sg0,
                            const float* __restrict__ sb0, const float* __restrict__ X)
{
    __shared__ float red[256];
    int b = blockIdx.x, tid = threadIdx.x;
    if (b < 2563) {
        const float* v; const float* g; int cols, r, mode; // 0=fp32,1=tf32,2=half
        float*  o32 = nullptr; __half* o16 = nullptr;
        if      (b < 512)  { v=mv0; g=mg0; o32=g_wmod0; cols=INCH; r=b;      mode=1; }
        else if (b < 1024) { v=mv1; g=mg1; o32=g_wmod1; cols=KCAT; r=b-512;  mode=1; }
        else if (b < 1536) { v=mv2; g=mg2; o32=g_wmod2; cols=KCAT; r=b-1024; mode=1; }
        else if (b < 2048) { v=sv1; g=sg1; o16=g_hW1;   cols=SH;   r=b-1536; mode=2; }
        else if (b < 2560) { v=sv2; g=sg2; o16=g_hW2;   cols=SH;   r=b-2048; mode=2; }
        else               { v=dv;  g=dg;  o32=g_wdec;  cols=SH;   r=b-2560; mode=0; }
        const float* vr = v + (size_t)r * cols;
        float ss = 0.f;
        for (int c = tid; c < cols; c += 256) { float x = vr[c]; ss += x * x; }
        red[tid] = ss; __syncthreads();
        for (int s = 128; s > 0; s >>= 1) {
            if (tid < s) red[tid] += red[tid + s];
            __syncthreads();
        }
        float scale = g[r] * rsqrtf(red[0]);
        for (int c = tid; c < cols; c += 256) {
            float w = vr[c] * scale;
            if (mode == 2)      o16[(size_t)r * cols + c] = __float2half(w);
            else if (mode == 1) o32[(size_t)r * cols + c] = rna_tf32(w);
            else                o32[(size_t)r * cols + c] = w;
        }
    } else if (b < 2662) {          // s0 table
        int p = b - 2563;
        float t = (float)p / 99.f;
        for (int j = tid; j < SH; j += 256) {
            float vv = sv0[j];
            float w  = sg0[j] * vv * rsqrtf(vv * vv);
            g_s0[p * SH + j] = sinf(SCALE0 * (t * w + sb0[j]));
        }
    } else {                        // X rounding + Z prefix
        int i0 = (b - 2662) * 256 + tid;
        for (int i = i0; i < NS * INCH; i += 64 * 256) {
            float v = rna_tf32(X[i]);
            int s = i >> 6, c = i & 63;
            g_Xr[i] = v;
            g_Z0[(size_t)s * KCAT + c] = v;
            g_Z1[(size_t)s * KCAT + c] = v;
        }
    }
}

// ================= mod GEMM (mma.sync tf32, silu, Z-writeback) — 64x128 tiles ====
#define BMM 64
#define BNM 128
#define BKM 32
#define SST 36
__global__ __launch_bounds__(256, 2)
void gemm_mod_kernel(const float* __restrict__ A, const float* __restrict__ W,
                     const float* __restrict__ bias, float* __restrict__ out,
                     float* __restrict__ zout, int K)
{
    extern __shared__ float sm[];
    float* sA = sm;
    float* sB = sm + 2 * BMM * SST;
    const int tid = threadIdx.x;
    const int rowBase = blockIdx.y * BMM;
    const int colBase = blockIdx.x * BNM;
    const uint32_t sA_u = (uint32_t)__cvta_generic_to_shared(sA);
    const uint32_t sB_u = (uint32_t)__cvta_generic_to_shared(sB);
    const int lane = tid & 31, warp = tid >> 5;
    const int wm = warp & 3, wn = warp >> 2;
    const int gg = lane >> 2, tt = lane & 3;
    float acc[8][4] = {};
    const int nk = K / BKM;

    auto load_stage = [&](int i, int buf){
        int k0 = i * BKM;
        #pragma unroll
        for (int it = 0; it < 2; it++){
            int c  = tid + it * 256;
            int r  = c >> 3;
            int kc = (c & 7) * 4;
            cp16(sA_u + (uint32_t)((buf * BMM * SST + r * SST + kc) * 4),
                 &A[(size_t)(rowBase + r) * K + k0 + kc]);
        }
        #pragma unroll
        for (int it = 0; it < 4; it++){
            int c  = tid + it * 256;
            int r  = c >> 3;
            int kc = (c & 7) * 4;
            cp16(sB_u + (uint32_t)((buf * BNM * SST + r * SST + kc) * 4),
                 &W[(size_t)(colBase + r) * K + k0 + kc]);
        }
        asm volatile("cp.async.commit_group;");
    };

    load_stage(0, 0);
    for (int i = 0; i < nk; i++){
        if (i + 1 < nk) { load_stage(i + 1, (i + 1) & 1); asm volatile("cp.async.wait_group 1;"); }
        else            { asm volatile("cp.async.wait_group 0;"); }
        __syncthreads();
        const float* cA = sA + (i & 1) * BMM * SST;
        const float* cB = sB + (i & 1) * BNM * SST;
        #pragma unroll
        for (int kk = 0; kk < BKM; kk += 8){
            uint32_t a[4], b[8][2];
            {
                int r = wm * 16 + gg;
                a[0] = __float_as_uint(cA[r * SST + kk + tt]);
                a[1] = __float_as_uint(cA[(r + 8) * SST + kk + tt]);
                a[2] = __float_as_uint(cA[r * SST + kk + tt + 4]);
                a[3] = __float_as_uint(cA[(r + 8) * SST + kk + tt + 4]);
            }
            #pragma unroll
            for (int ni = 0; ni < 8; ni++){
                int c = wn * 64 + ni * 8 + gg;
                b[ni][0] = __float_as_uint(cB[c * SST + kk + tt]);
                b[ni][1] = __float_as_uint(cB[c * SST + kk + tt + 4]);
            }
            #pragma unroll
            for (int ni = 0; ni < 8; ni++){
                float* d = acc[ni];
                asm volatile(
                    "mma.sync.aligned.m16n8k8.row.col.f32.tf32.tf32.f32 "
                    "{%0,%1,%2,%3}, {%4,%5,%6,%7}, {%8,%9}, {%0,%1,%2,%3};"
                    : "+f"(d[0]), "+f"(d[1]), "+f"(d[2]), "+f"(d[3])
                    : "r"(a[0]), "r"(a[1]), "r"(a[2]), "r"(a[3]),
                      "r"(b[ni][0]), "r"(b[ni][1]));
            }
        }
        __syncthreads();
    }

    int row0 = rowBase + wm * 16 + gg;
    #pragma unroll
    for (int ni = 0; ni < 8; ni++){
        int col = colBase + wn * 64 + ni * 8 + tt * 2;
        float b0 = bias[col], b1 = bias[col + 1];
        #pragma unroll
        for (int h = 0; h < 2; h++){
            int row = row0 + h * 8;
            float v0 = acc[ni][h * 2 + 0] + b0;
            float v1 = acc[ni][h * 2 + 1] + b1;
            v0 = v0 / (1.f + __expf(-v0));
            v1 = v1 / (1.f + __expf(-v1));
            *reinterpret_cast<float2*>(&out[(size_t)row * 512 + col]) = make_float2(v0, v1);
            if (zout)
                *reinterpret_cast<float2*>(&zout[(size_t)row * KCAT + 64 + col]) =
                    make_float2(rna_tf32(v0), rna_tf32(v1));
        }
    }
}

// ================= fp16 tensor-core GEMM (101376 x 512 x 512), 3-stage pipeline ==
// MODE 1: A computed on the fly = half((1-gateA[strand,k])*s0[p,k]); epilogue stores
//         half out = (1-gateE)*sin(acc+bias).
// MODE 2: A loaded from half; epilogue feeds fused decoder (atomicAdd into g_dir).
#define BK2 64
#define TC_STAGES 3

template<int MODE>
__global__ __launch_bounds__(256, 2)
void tc_fp16_kernel(const __half* __restrict__ A, const __half* __restrict__ W,
                    const float* __restrict__ bias, const float* __restrict__ gateE,
                    const float* __restrict__ gateA, __half* __restrict__ out)
{
    extern __shared__ __align__(1024) char smem_raw[];
    uint32_t base  = (uint32_t)__cvta_generic_to_shared(smem_raw);
    uint32_t abase = (base + 1023u) & ~1023u;
    const int tid = threadIdx.x, warp = tid >> 5, lane = tid & 31;
    const int rowBase = blockIdx.y * 128, colBase = blockIdx.x * 128;
    const int wm = warp & 3, wn = warp >> 2;
    const int gl = (lane >> 3) & 1, gh = lane >> 4, lr = lane & 7;

    // decoder weight slice (MODE 2)
    float* wds = reinterpret_cast<float*>(smem_raw + (abase - base) + TC_STAGES * 32768);
    if (MODE == 2 && tid < 128) {
        #pragma unroll
        for (int d = 0; d < 3; d++)
            wds[d * 128 + tid] = g_wdec[d * 512 + colBase + tid];
    }

    auto load_B = [&](int t, int buf){
        uint32_t bBuf = abase + buf * 32768 + 16384;
        int k0 = t * BK2;
        #pragma unroll
        for (int it = 0; it < 4; it++){
            int idx = tid + it * 256;
            int r = idx >> 3, c = idx & 7;
            uint32_t off = (uint32_t)(r * 128 + ((c ^ (r & 7)) * 16));
            cp16(bBuf + off, &W[(size_t)(colBase + r) * 512 + k0 + c * 8]);
        }
    };
    auto load_A = [&](int t, int buf){
        uint32_t aBuf = abase + buf * 32768;
        int k0 = t * BK2;
        #pragma unroll
        for (int it = 0; it < 4; it++){
            int idx = tid + it * 256;
            int r = idx >> 3, c = idx & 7;
            uint32_t off = (uint32_t)(r * 128 + ((c ^ (r & 7)) * 16));
            cp16(aBuf + off, &A[(size_t)(rowBase + r) * 512 + k0 + c * 8]);
        }
    };
    auto produce_A = [&](int t, int buf){           // MODE 1: (1-M0)*s0 -> half smem
        uint32_t aBuf = abase + buf * 32768;
        int k0 = t * BK2;
        #pragma unroll
        for (int it = 0; it < 4; it++){
            int idx = tid + it * 256;
            int r = idx >> 3, c = idx & 7;
            int row = rowBase + r;
            int strand = row / NV, p = row - strand * NV;
            const float4* m4 = reinterpret_cast<const float4*>(&gateA[(size_t)strand * MH + k0 + c * 8]);
            const float4* s4 = reinterpret_cast<const float4*>(&g_s0[p * SH + k0 + c * 8]);
            float4 m0 = m4[0], m1 = m4[1], s0v = s4[0], s1v = s4[1];
            __half2 h0 = __floats2half2_rn((1.f - m0.x) * s0v.x, (1.f - m0.y) * s0v.y);
            __half2 h1 = __floats2half2_rn((1.f - m0.z) * s0v.z, (1.f - m0.w) * s0v.w);
            __half2 h2 = __floats2half2_rn((1.f - m1.x) * s1v.x, (1.f - m1.y) * s1v.y);
            __half2 h3 = __floats2half2_rn((1.f - m1.z) * s1v.z, (1.f - m1.w) * s1v.w);
            uint32_t off = (uint32_t)(r * 128 + ((c ^ (r & 7)) * 16));
            asm volatile("st.shared.v4.b32 [%0], {%1,%2,%3,%4};"
                         :: "r"(aBuf + off),
                            "r"(*reinterpret_cast<uint32_t*>(&h0)),
                            "r"(*reinterpret_cast<uint32_t*>(&h1)),
                            "r"(*reinterpret_cast<uint32_t*>(&h2)),
                            "r"(*reinterpret_cast<uint32_t*>(&h3)) : "memory");
        }
    };
    auto load_stage = [&](int t, int buf){
        if (MODE == 1) produce_A(t, buf); else load_A(t, buf);
        load_B(t, buf);
        asm volatile("cp.async.commit_group;");
    };

    float acc[2][8][4] = {};

    load_stage(0, 0);
    load_stage(1, 1);
    load_stage(2, 2);

    for (int t = 0; t < 8; t++){
        if (t < 7) asm volatile("cp.async.wait_group 2;" ::: "memory");
        else       asm volatile("cp.async.wait_group 0;" ::: "memory");
        __syncthreads();
        int buf = t % TC_STAGES;
        uint32_t aBuf = abase + buf * 32768;
        uint32_t bBuf = aBuf + 16384;

        #pragma unroll
        for (int kk = 0; kk < 4; kk++){
            int kc = kk * 2 + gh;
            uint32_t a[2][4], b[4][4];
            #pragma unroll
            for (int mi = 0; mi < 2; mi++){
                int row = wm * 32 + mi * 16 + gl * 8 + lr;
                ldsm4(a[mi][0], a[mi][1], a[mi][2], a[mi][3],
                      aBuf + (uint32_t)(row * 128 + ((kc ^ lr) * 16)));
            }
            #pragma unroll
            for (int nq = 0; nq < 4; nq++){
                int nrow = wn * 64 + nq * 16 + gl * 8 + lr;
                ldsm4(b[nq][0], b[nq][1], b[nq][2], b[nq][3],
                      bBuf + (uint32_t)(nrow * 128 + ((kc ^ lr) * 16)));
            }
            #pragma unroll
            for (int mi = 0; mi < 2; mi++)
                #pragma unroll
                for (int nq = 0; nq < 4; nq++){
                    #pragma unroll
                    for (int hf = 0; hf < 2; hf++){
                        float* d = acc[mi][nq * 2 + hf];
                        asm volatile(
                            "mma.sync.aligned.m16n8k16.row.col.f32.f16.f16.f32 "
                            "{%0,%1,%2,%3}, {%4,%5,%6,%7}, {%8,%9}, {%0,%1,%2,%3};"
                            : "+f"(d[0]), "+f"(d[1]), "+f"(d[2]), "+f"(d[3])
                            : "r"(a[mi][0]), "r"(a[mi][1]), "r"(a[mi][2]), "r"(a[mi][3]),
                              "r"(b[nq][hf]), "r"(b[nq][2 + hf]));
                    }
                }
        }
        __syncthreads();
        if (t + 3 < 8) load_stage(t + 3, (t + 3) % TC_STAGES);
    }

    // ---- epilogue ----
    const int gg = lane >> 2, tt = lane & 3;
    float p3[4][3];
    if (MODE == 2){
        #pragma unroll
        for (int q = 0; q < 4; q++){ p3[q][0] = 0.f; p3[q][1] = 0.f; p3[q][2] = 0.f; }
    }
    #pragma unroll
    for (int mi = 0; mi < 2; mi++){
        int row0 = rowBase + wm * 32 + mi * 16 + gg;
        #pragma unroll
        for (int ni = 0; ni < 8; ni++){
            int col = colBase + wn * 64 + ni * 8 + tt * 2;
            float b0 = bias[col], b1 = bias[col + 1];
            #pragma unroll
            for (int h = 0; h < 2; h++){
                int row = row0 + h * 8;
                int strand = row / NV;
                float g0 = 1.f - gateE[(size_t)strand * MH + col];
                float g1 = 1.f - gateE[(size_t)strand * MH + col + 1];
                float v0 = g0 * __sinf(acc[mi][ni][h * 2 + 0] + b0);
                float v1 = g1 * __sinf(acc[mi][ni][h * 2 + 1] + b1);
                if (MODE == 1){
                    *reinterpret_cast<__half2*>(&out[(size_t)row * 512 + col]) =
                        __floats2half2_rn(v0, v1);
                } else {
                    int lc = col - colBase;
                    int q = mi * 2 + h;
                    #pragma unroll
                    for (int d = 0; d < 3; d++)
                        p3[q][d] += v0 * wds[d * 128 + lc] + v1 * wds[d * 128 + lc + 1];
                }
            }
        }
    }
    if (MODE == 2){
        #pragma unroll
        for (int q = 0; q < 4; q++)
            #pragma unroll
            for (int d = 0; d < 3; d++){
                float v = p3[q][d];
                v += __shfl_xor_sync(0xFFFFFFFFu, v, 1);
                v += __shfl_xor_sync(0xFFFFFFFFu, v, 2);
                p3[q][d] = v;
            }
        if (tt == 0){
            int rb = rowBase + wm * 32 + gg;
            #pragma unroll
            for (int q = 0; q < 4; q++){
                int row = rb + (q & 1) * 8 + (q >> 1) * 16;
                #pragma unroll
                for (int d = 0; d < 3; d++)
                    atomicAdd(&g_dir[(size_t)row * 3 + d], p3[q][d] * 0.01f);
            }
        }
    }
}

// ================= cumsum (adds decoder bias per step) =================
__global__ void cumsum_kernel(float* __restrict__ out, const float* __restrict__ bd)
{
    int idx = blockIdx.x * blockDim.x + threadIdx.x;
    if (idx >= NS * 3) return;
    int s = idx / 3, d = idx - s * 3;
    float bias = bd[d] * 0.01f;
    float acc = 0.f;
    out[(size_t)s * 300 + d] = 0.f;
    for (int p = 0; p < NV; p++) {
        acc += g_dir[((size_t)s * NV + p) * 3 + d] + bias;
        out[(size_t)s * 300 + (size_t)(p + 1) * 3 + d] = acc;
    }
}

// ================= host launch =================
static void* sym(const void* s) { void* p = nullptr; cudaGetSymbolAddress(&p, s); return p; }

extern "C" void kernel_launch(void* const* d_in, const int* in_sizes, int n_in,
                              void* d_out, int out_size)
{
    const float* X   = (const float*)d_in[0];
    const float* mv0 = (const float*)d_in[1];  const float* mg0 = (const float*)d_in[2];  const float* mb0 = (const float*)d_in[3];
    const float* mv1 = (const float*)d_in[4];  const float* mg1 = (const float*)d_in[5];  const float* mb1 = (const float*)d_in[6];
    const float* mv2 = (const float*)d_in[7];  const float* mg2 = (const float*)d_in[8];  const float* mb2 = (const float*)d_in[9];
    const float* sv0 = (const float*)d_in[10]; const float* sg0 = (const float*)d_in[11]; const float* sb0 = (const float*)d_in[12];
    const float* sv1 = (const float*)d_in[13]; const float* sg1 = (const float*)d_in[14]; const float* sb1 = (const float*)d_in[15];
    const float* sv2 = (const float*)d_in[16]; const float* sg2 = (const float*)d_in[17]; const float* sb2 = (const float*)d_in[18];
    const float* dv  = (const float*)d_in[19]; const float* dg  = (const float*)d_in[20]; const float* db  = (const float*)d_in[21];
    float* out = (float*)d_out;

    float*  wmod0 = (float*)sym(g_wmod0);
    float*  wmod1 = (float*)sym(g_wmod1);
    float*  wmod2 = (float*)sym(g_wmod2);
    __half* hW1   = (__half*)sym(g_hW1);
    __half* hW2   = (__half*)sym(g_hW2);
    float*  M0    = (float*)sym(g_M0);
    float*  M1    = (float*)sym(g_M1);
    float*  M2    = (float*)sym(g_M2);
    float*  Z0    = (float*)sym(g_Z0);
    float*  Z1    = (float*)sym(g_Z1);
    float*  Xr    = (float*)sym(g_Xr);
    __half* hHB   = (__half*)sym(g_hHB);
    float*  dir   = (float*)sym(g_dir);

    const int mod_smem = 2 * (BMM + BNM) * SST * 4;          // 55296
    const int tc_smem  = TC_STAGES * 32768 + 2048 + 1024;    // 101376
    static int attr_done = 0;
    static cudaStream_t s2 = nullptr;
    static cudaEvent_t ev1 = nullptr, ev2 = nullptr;
    if (!attr_done) {
        cudaFuncSetAttribute(gemm_mod_kernel, cudaFuncAttributeMaxDynamicSharedMemorySize, mod_smem);
        cudaFuncSetAttribute(tc_fp16_kernel<1>, cudaFuncAttributeMaxDynamicSharedMemorySize, tc_smem);
        cudaFuncSetAttribute(tc_fp16_kernel<2>, cudaFuncAttributeMaxDynamicSharedMemorySize, tc_smem);
        cudaStreamCreateWithFlags(&s2, cudaStreamNonBlocking);
        cudaEventCreateWithFlags(&ev1, cudaEventDisableTiming);
        cudaEventCreateWithFlags(&ev2, cudaEventDisableTiming);
        attr_done = 1;
    }

    // prep (stream 0)
    prep_kernel<<<2726, 256>>>(mv0, mg0, mv1, mg1, mv2, mg2, sv1, sg1, sv2, sg2,
                               dv, dg, sv0, sg0, sb0, X);

    // mod0, mod1 (stream 0)
    {
        dim3 grid(512 / BNM, NS / BMM);
        gemm_mod_kernel<<<grid, 256, mod_smem>>>(Xr, wmod0, mb0, M0, Z0, INCH);
        gemm_mod_kernel<<<grid, 256, mod_smem>>>(Z0, wmod1, mb1, M1, Z1, KCAT);
        // fork: mod2 runs on s2 concurrently with GEMM1
        cudaEventRecord(ev1, 0);
        cudaStreamWaitEvent(s2, ev1, 0);
        gemm_mod_kernel<<<grid, 256, mod_smem, s2>>>(Z1, wmod2, mb2, M2, nullptr, KCAT);
        cudaEventRecord(ev2, s2);
    }

    // zero decoder accumulator, then GEMM1 (stream 0, overlapped with mod2)
    cudaMemsetAsync(dir, 0, (size_t)ROWS * 3 * sizeof(float), 0);
    {
        dim3 grid(512 / 128, ROWS / 128);
        tc_fp16_kernel<1><<<grid, 256, tc_smem>>>(nullptr, hW1, sb1, M1, M0, hHB);
        // join: GEMM2 needs M2 from mod2
        cudaStreamWaitEvent(0, ev2, 0);
        tc_fp16_kernel<2><<<grid, 256, tc_smem>>>(hHB, hW2, sb2, M2, nullptr, nullptr);
    }

    // cumsum (stream 0)
    cumsum_kernel<<<(NS * 3 + 255) / 256, 256>>>(out, db);
    (void)in_sizes; (void)n_in; (void)out_size;
}

// round 12
// speedup vs baseline: 1.3134x; 1.0191x over previous
#include <cuda_runtime.h>
#include <cuda_fp16.h>
#include <cstdint>

// ---------------- problem constants ----------------
#define NS      1024
#define NV      99
#define ROWS    (NS*NV)       // 101376
#define INCH    64
#define MH      512
#define SH      512
#define KCAT    (INCH+MH)     // 576
#define SCALE0  30.0f

// ---------------- device scratch ----------------
__device__ float  g_wmod0[MH*INCH];
__device__ float  g_wmod1[MH*KCAT];
__device__ float  g_wmod2[MH*KCAT];
__device__ __half g_hW1[SH*SH];
__device__ __half g_hW2[SH*SH];
__device__ float  g_wdec[3*SH];
__device__ float  g_s0[NV*SH];
__device__ float  g_M0[NS*MH];
__device__ float  g_M1[NS*MH];
__device__ float  g_M2[NS*MH];
__device__ float  g_Z0[NS*KCAT];
__device__ float  g_Z1[NS*KCAT];
__device__ float  g_Xr[NS*INCH];
__device__ __half g_hHB[(size_t)ROWS*SH];
__device__ float  g_dir[(size_t)ROWS*3];

__device__ __forceinline__ float rna_tf32(float x){
    float y; asm("cvt.rna.tf32.f32 %0, %1;" : "=f"(y) : "f"(x)); return y;
}
__device__ __forceinline__ void cp16(uint32_t s, const void* g){
    asm volatile("cp.async.cg.shared.global [%0], [%1], 16;" :: "r"(s), "l"(g));
}
__device__ __forceinline__ void ldsm4(uint32_t& r0, uint32_t& r1, uint32_t& r2, uint32_t& r3,
                                      uint32_t addr){
    asm volatile("ldmatrix.sync.aligned.m8n8.x4.shared.b16 {%0,%1,%2,%3}, [%4];"
                 : "=r"(r0), "=r"(r1), "=r"(r2), "=r"(r3) : "r"(addr));
}

// ---------------- shared rownorm body ----------------
__device__ __forceinline__ void rownorm_row(const float* __restrict__ v,
                                            const float* __restrict__ g,
                                            float* o32, __half* o16,
                                            int cols, int r, int mode, int tid,
                                            float* red)
{
    const float* vr = v + (size_t)r * cols;
    float ss = 0.f;
    for (int c = tid; c < cols; c += 256) { float x = vr[c]; ss += x * x; }
    red[tid] = ss; __syncthreads();
    for (int s = 128; s > 0; s >>= 1) {
        if (tid < s) red[tid] += red[tid + s];
        __syncthreads();
    }
    float scale = g[r] * rsqrtf(red[0]);
    for (int c = tid; c < cols; c += 256) {
        float w = vr[c] * scale;
        if (mode == 2)      o16[(size_t)r * cols + c] = __float2half(w);
        else if (mode == 1) o32[(size_t)r * cols + c] = rna_tf32(w);
        else                o32[(size_t)r * cols + c] = w;
    }
}

// ================= prep_crit: mod weight-norms + X rounding (critical path) ======
__global__ void prep_crit_kernel(const float* __restrict__ mv0, const float* __restrict__ mg0,
                                 const float* __restrict__ mv1, const float* __restrict__ mg1,
                                 const float* __restrict__ mv2, const float* __restrict__ mg2,
                                 const float* __restrict__ X)
{
    __shared__ float red[256];
    int b = blockIdx.x, tid = threadIdx.x;
    if (b < 1536) {
        if      (b < 512)  rownorm_row(mv0, mg0, g_wmod0, nullptr, INCH, b,        1, tid, red);
        else if (b < 1024) rownorm_row(mv1, mg1, g_wmod1, nullptr, KCAT, b - 512,  1, tid, red);
        else               rownorm_row(mv2, mg2, g_wmod2, nullptr, KCAT, b - 1024, 1, tid, red);
    } else {
        int i0 = (b - 1536) * 256 + tid;
        for (int i = i0; i < NS * INCH; i += 64 * 256) {
            float v = rna_tf32(X[i]);
            int s = i >> 6, c = i & 63;
            g_Xr[i] = v;
            g_Z0[(size_t)s * KCAT + c] = v;
            g_Z1[(size_t)s * KCAT + c] = v;
        }
    }
}

// ================= prep_rest: siren weight-norms + s0 table (off critical path) ==
__global__ void prep_rest_kernel(const float* __restrict__ sv1, const float* __restrict__ sg1,
                                 const float* __restrict__ sv2, const float* __restrict__ sg2,
                                 const float* __restrict__ dv,  const float* __restrict__ dg,
                                 const float* __restrict__ sv0, const float* __restrict__ sg0,
                                 const float* __restrict__ sb0)
{
    __shared__ float red[256];
    int b = blockIdx.x, tid = threadIdx.x;
    if (b < 1025) {
        if      (b < 512)  rownorm_row(sv1, sg1, nullptr, g_hW1, SH, b,       2, tid, red);
        else if (b < 1024) rownorm_row(sv2, sg2, nullptr, g_hW2, SH, b - 512, 2, tid, red);
        else {
            for (int r = 0; r < 3; r++) rownorm_row(dv, dg, g_wdec, nullptr, SH, r, 0, tid, red);
        }
    } else {                            // s0 table: 99 blocks
        int p = b - 1025;
        float t = (float)p / 99.f;
        for (int j = tid; j < SH; j += 256) {
            float vv = sv0[j];
            float w  = sg0[j] * vv * rsqrtf(vv * vv);
            g_s0[p * SH + j] = sinf(SCALE0 * (t * w + sb0[j]));
        }
    }
}

// ================= mod GEMM (mma.sync tf32, silu, Z-writeback) — 64x64 tiles =====
#define BMM 64
#define BNM 64
#define BKM 32
#define SST 36
__global__ __launch_bounds__(256, 2)
void gemm_mod_kernel(const float* __restrict__ A, const float* __restrict__ W,
                     const float* __restrict__ bias, float* __restrict__ out,
                     float* __restrict__ zout, int K)
{
    extern __shared__ float sm[];
    float* sA = sm;
    float* sB = sm + 2 * BMM * SST;
    const int tid = threadIdx.x;
    const int rowBase = blockIdx.y * BMM;
    const int colBase = blockIdx.x * BNM;
    const uint32_t sA_u = (uint32_t)__cvta_generic_to_shared(sA);
    const uint32_t sB_u = (uint32_t)__cvta_generic_to_shared(sB);
    const int lane = tid & 31, warp = tid >> 5;
    const int wm = warp & 3, wn = warp >> 2;     // warp tile 16 x 32
    const int gg = lane >> 2, tt = lane & 3;
    float acc[4][4] = {};
    const int nk = K / BKM;

    auto load_stage = [&](int i, int buf){
        int k0 = i * BKM;
        #pragma unroll
        for (int it = 0; it < 2; it++){
            int c  = tid + it * 256;
            int r  = c >> 3;
            int kc = (c & 7) * 4;
            cp16(sA_u + (uint32_t)((buf * BMM * SST + r * SST + kc) * 4),
                 &A[(size_t)(rowBase + r) * K + k0 + kc]);
            cp16(sB_u + (uint32_t)((buf * BNM * SST + r * SST + kc) * 4),
                 &W[(size_t)(colBase + r) * K + k0 + kc]);
        }
        asm volatile("cp.async.commit_group;");
    };

    load_stage(0, 0);
    for (int i = 0; i < nk; i++){
        if (i + 1 < nk) { load_stage(i + 1, (i + 1) & 1); asm volatile("cp.async.wait_group 1;"); }
        else            { asm volatile("cp.async.wait_group 0;"); }
        __syncthreads();
        const float* cA = sA + (i & 1) * BMM * SST;
        const float* cB = sB + (i & 1) * BNM * SST;
        #pragma unroll
        for (int kk = 0; kk < BKM; kk += 8){
            uint32_t a[4], b[4][2];
            {
                int r = wm * 16 + gg;
                a[0] = __float_as_uint(cA[r * SST + kk + tt]);
                a[1] = __float_as_uint(cA[(r + 8) * SST + kk + tt]);
                a[2] = __float_as_uint(cA[r * SST + kk + tt + 4]);
                a[3] = __float_as_uint(cA[(r + 8) * SST + kk + tt + 4]);
            }
            #pragma unroll
            for (int ni = 0; ni < 4; ni++){
                int c = wn * 32 + ni * 8 + gg;
                b[ni][0] = __float_as_uint(cB[c * SST + kk + tt]);
                b[ni][1] = __float_as_uint(cB[c * SST + kk + tt + 4]);
            }
            #pragma unroll
            for (int ni = 0; ni < 4; ni++){
                float* d = acc[ni];
                asm volatile(
                    "mma.sync.aligned.m16n8k8.row.col.f32.tf32.tf32.f32 "
                    "{%0,%1,%2,%3}, {%4,%5,%6,%7}, {%8,%9}, {%0,%1,%2,%3};"
                    : "+f"(d[0]), "+f"(d[1]), "+f"(d[2]), "+f"(d[3])
                    : "r"(a[0]), "r"(a[1]), "r"(a[2]), "r"(a[3]),
                      "r"(b[ni][0]), "r"(b[ni][1]));
            }
        }
        __syncthreads();
    }

    int row0 = rowBase + wm * 16 + gg;
    #pragma unroll
    for (int ni = 0; ni < 4; ni++){
        int col = colBase + wn * 32 + ni * 8 + tt * 2;
        float b0 = bias[col], b1 = bias[col + 1];
        #pragma unroll
        for (int h = 0; h < 2; h++){
            int row = row0 + h * 8;
            float v0 = acc[ni][h * 2 + 0] + b0;
            float v1 = acc[ni][h * 2 + 1] + b1;
            v0 = v0 / (1.f + __expf(-v0));
            v1 = v1 / (1.f + __expf(-v1));
            *reinterpret_cast<float2*>(&out[(size_t)row * 512 + col]) = make_float2(v0, v1);
            if (zout)
                *reinterpret_cast<float2*>(&zout[(size_t)row * KCAT + 64 + col]) =
                    make_float2(rna_tf32(v0), rna_tf32(v1));
        }
    }
}

// ================= fp16 tensor-core GEMM (101376 x 512 x 512), 3-stage pipeline ==
#define BK2 64
#define TC_STAGES 3

template<int MODE>
__global__ __launch_bounds__(256, 2)
void tc_fp16_kernel(const __half* __restrict__ A, const __half* __restrict__ W,
                    const float* __restrict__ bias, const float* __restrict__ gateE,
                    const float* __restrict__ gateA, __half* __restrict__ out)
{
    extern __shared__ __align__(1024) char smem_raw[];
    uint32_t base  = (uint32_t)__cvta_generic_to_shared(smem_raw);
    uint32_t abase = (base + 1023u) & ~1023u;
    const int tid = threadIdx.x, warp = tid >> 5, lane = tid & 31;
    const int rowBase = blockIdx.y * 128, colBase = blockIdx.x * 128;
    const int wm = warp & 3, wn = warp >> 2;
    const int gl = (lane >> 3) & 1, gh = lane >> 4, lr = lane & 7;

    float* wds = reinterpret_cast<float*>(smem_raw + (abase - base) + TC_STAGES * 32768);
    if (MODE == 2 && tid < 128) {
        #pragma unroll
        for (int d = 0; d < 3; d++)
            wds[d * 128 + tid] = g_wdec[d * 512 + colBase + tid];
    }

    auto load_B = [&](int t, int buf){
        uint32_t bBuf = abase + buf * 32768 + 16384;
        int k0 = t * BK2;
        #pragma unroll
        for (int it = 0; it < 4; it++){
            int idx = tid + it * 256;
            int r = idx >> 3, c = idx & 7;
            uint32_t off = (uint32_t)(r * 128 + ((c ^ (r & 7)) * 16));
            cp16(bBuf + off, &W[(size_t)(colBase + r) * 512 + k0 + c * 8]);
        }
    };
    auto load_A = [&](int t, int buf){
        uint32_t aBuf = abase + buf * 32768;
        int k0 = t * BK2;
        #pragma unroll
        for (int it = 0; it < 4; it++){
            int idx = tid + it * 256;
            int r = idx >> 3, c = idx & 7;
            uint32_t off = (uint32_t)(r * 128 + ((c ^ (r & 7)) * 16));
            cp16(aBuf + off, &A[(size_t)(rowBase + r) * 512 + k0 + c * 8]);
        }
    };
    auto produce_A = [&](int t, int buf){
        uint32_t aBuf = abase + buf * 32768;
        int k0 = t * BK2;
        #pragma unroll
        for (int it = 0; it < 4; it++){
            int idx = tid + it * 256;
            int r = idx >> 3, c = idx & 7;
            int row = rowBase + r;
            int strand = row / NV, p = row - strand * NV;
            const float4* m4 = reinterpret_cast<const float4*>(&gateA[(size_t)strand * MH + k0 + c * 8]);
            const float4* s4 = reinterpret_cast<const float4*>(&g_s0[p * SH + k0 + c * 8]);
            float4 m0 = m4[0], m1 = m4[1], s0v = s4[0], s1v = s4[1];
            __half2 h0 = __floats2half2_rn((1.f - m0.x) * s0v.x, (1.f - m0.y) * s0v.y);
            __half2 h1 = __floats2half2_rn((1.f - m0.z) * s0v.z, (1.f - m0.w) * s0v.w);
            __half2 h2 = __floats2half2_rn((1.f - m1.x) * s1v.x, (1.f - m1.y) * s1v.y);
            __half2 h3 = __floats2half2_rn((1.f - m1.z) * s1v.z, (1.f - m1.w) * s1v.w);
            uint32_t off = (uint32_t)(r * 128 + ((c ^ (r & 7)) * 16));
            asm volatile("st.shared.v4.b32 [%0], {%1,%2,%3,%4};"
                         :: "r"(aBuf + off),
                            "r"(*reinterpret_cast<uint32_t*>(&h0)),
                            "r"(*reinterpret_cast<uint32_t*>(&h1)),
                            "r"(*reinterpret_cast<uint32_t*>(&h2)),
                            "r"(*reinterpret_cast<uint32_t*>(&h3)) : "memory");
        }
    };
    auto load_stage = [&](int t, int buf){
        if (MODE == 1) produce_A(t, buf); else load_A(t, buf);
        load_B(t, buf);
        asm volatile("cp.async.commit_group;");
    };

    float acc[2][8][4] = {};

    load_stage(0, 0);
    load_stage(1, 1);
    load_stage(2, 2);

    for (int t = 0; t < 8; t++){
        if (t < 7) asm volatile("cp.async.wait_group 2;" ::: "memory");
        else       asm volatile("cp.async.wait_group 0;" ::: "memory");
        __syncthreads();
        int buf = t % TC_STAGES;
        uint32_t aBuf = abase + buf * 32768;
        uint32_t bBuf = aBuf + 16384;

        #pragma unroll
        for (int kk = 0; kk < 4; kk++){
            int kc = kk * 2 + gh;
            uint32_t a[2][4], b[4][4];
            #pragma unroll
            for (int mi = 0; mi < 2; mi++){
                int row = wm * 32 + mi * 16 + gl * 8 + lr;
                ldsm4(a[mi][0], a[mi][1], a[mi][2], a[mi][3],
                      aBuf + (uint32_t)(row * 128 + ((kc ^ lr) * 16)));
            }
            #pragma unroll
            for (int nq = 0; nq < 4; nq++){
                int nrow = wn * 64 + nq * 16 + gl * 8 + lr;
                ldsm4(b[nq][0], b[nq][1], b[nq][2], b[nq][3],
                      bBuf + (uint32_t)(nrow * 128 + ((kc ^ lr) * 16)));
            }
            #pragma unroll
            for (int mi = 0; mi < 2; mi++)
                #pragma unroll
                for (int nq = 0; nq < 4; nq++){
                    #pragma unroll
                    for (int hf = 0; hf < 2; hf++){
                        float* d = acc[mi][nq * 2 + hf];
                        asm volatile(
                            "mma.sync.aligned.m16n8k16.row.col.f32.f16.f16.f32 "
                            "{%0,%1,%2,%3}, {%4,%5,%6,%7}, {%8,%9}, {%0,%1,%2,%3};"
                            : "+f"(d[0]), "+f"(d[1]), "+f"(d[2]), "+f"(d[3])
                            : "r"(a[mi][0]), "r"(a[mi][1]), "r"(a[mi][2]), "r"(a[mi][3]),
                              "r"(b[nq][hf]), "r"(b[nq][2 + hf]));
                    }
                }
        }
        __syncthreads();
        if (t + 3 < 8) load_stage(t + 3, (t + 3) % TC_STAGES);
    }

    // ---- epilogue ----
    const int gg = lane >> 2, tt = lane & 3;
    float p3[4][3];
    if (MODE == 2){
        #pragma unroll
        for (int q = 0; q < 4; q++){ p3[q][0] = 0.f; p3[q][1] = 0.f; p3[q][2] = 0.f; }
    }
    #pragma unroll
    for (int mi = 0; mi < 2; mi++){
        int row0 = rowBase + wm * 32 + mi * 16 + gg;
        #pragma unroll
        for (int ni = 0; ni < 8; ni++){
            int col = colBase + wn * 64 + ni * 8 + tt * 2;
            float b0 = bias[col], b1 = bias[col + 1];
            #pragma unroll
            for (int h = 0; h < 2; h++){
                int row = row0 + h * 8;
                int strand = row / NV;
                float g0 = 1.f - gateE[(size_t)strand * MH + col];
                float g1 = 1.f - gateE[(size_t)strand * MH + col + 1];
                float v0 = g0 * __sinf(acc[mi][ni][h * 2 + 0] + b0);
                float v1 = g1 * __sinf(acc[mi][ni][h * 2 + 1] + b1);
                if (MODE == 1){
                    *reinterpret_cast<__half2*>(&out[(size_t)row * 512 + col]) =
                        __floats2half2_rn(v0, v1);
                } else {
                    int lc = col - colBase;
                    int q = mi * 2 + h;
                    #pragma unroll
                    for (int d = 0; d < 3; d++)
                        p3[q][d] += v0 * wds[d * 128 + lc] + v1 * wds[d * 128 + lc + 1];
                }
            }
        }
    }
    if (MODE == 2){
        #pragma unroll
        for (int q = 0; q < 4; q++)
            #pragma unroll
            for (int d = 0; d < 3; d++){
                float v = p3[q][d];
                v += __shfl_xor_sync(0xFFFFFFFFu, v, 1);
                v += __shfl_xor_sync(0xFFFFFFFFu, v, 2);
                p3[q][d] = v;
            }
        if (tt == 0){
            int rb = rowBase + wm * 32 + gg;
            #pragma unroll
            for (int q = 0; q < 4; q++){
                int row = rb + (q & 1) * 8 + (q >> 1) * 16;
                #pragma unroll
                for (int d = 0; d < 3; d++)
                    atomicAdd(&g_dir[(size_t)row * 3 + d], p3[q][d] * 0.01f);
            }
        }
    }
}

// ================= cumsum (adds decoder bias per step) =================
__global__ void cumsum_kernel(float* __restrict__ out, const float* __restrict__ bd)
{
    int idx = blockIdx.x * blockDim.x + threadIdx.x;
    if (idx >= NS * 3) return;
    int s = idx / 3, d = idx - s * 3;
    float bias = bd[d] * 0.01f;
    float acc = 0.f;
    out[(size_t)s * 300 + d] = 0.f;
    for (int p = 0; p < NV; p++) {
        acc += g_dir[((size_t)s * NV + p) * 3 + d] + bias;
        out[(size_t)s * 300 + (size_t)(p + 1) * 3 + d] = acc;
    }
}

// ================= host launch =================
static void* sym(const void* s) { void* p = nullptr; cudaGetSymbolAddress(&p, s); return p; }

extern "C" void kernel_launch(void* const* d_in, const int* in_sizes, int n_in,
                              void* d_out, int out_size)
{
    const float* X   = (const float*)d_in[0];
    const float* mv0 = (const float*)d_in[1];  const float* mg0 = (const float*)d_in[2];  const float* mb0 = (const float*)d_in[3];
    const float* mv1 = (const float*)d_in[4];  const float* mg1 = (const float*)d_in[5];  const float* mb1 = (const float*)d_in[6];
    const float* mv2 = (const float*)d_in[7];  const float* mg2 = (const float*)d_in[8];  const float* mb2 = (const float*)d_in[9];
    const float* sv0 = (const float*)d_in[10]; const float* sg0 = (const float*)d_in[11]; const float* sb0 = (const float*)d_in[12];
    const float* sv1 = (const float*)d_in[13]; const float* sg1 = (const float*)d_in[14]; const float* sb1 = (const float*)d_in[15];
    const float* sv2 = (const float*)d_in[16]; const float* sg2 = (const float*)d_in[17]; const float* sb2 = (const float*)d_in[18];
    const float* dv  = (const float*)d_in[19]; const float* dg  = (const float*)d_in[20]; const float* db  = (const float*)d_in[21];
    float* out = (float*)d_out;

    float*  wmod0 = (float*)sym(g_wmod0);
    float*  wmod1 = (float*)sym(g_wmod1);
    float*  wmod2 = (float*)sym(g_wmod2);
    __half* hW1   = (__half*)sym(g_hW1);
    __half* hW2   = (__half*)sym(g_hW2);
    float*  M0    = (float*)sym(g_M0);
    float*  M1    = (float*)sym(g_M1);
    float*  M2    = (float*)sym(g_M2);
    float*  Z0    = (float*)sym(g_Z0);
    float*  Z1    = (float*)sym(g_Z1);
    float*  Xr    = (float*)sym(g_Xr);
    __half* hHB   = (__half*)sym(g_hHB);
    float*  dir   = (float*)sym(g_dir);

    const int mod_smem = 2 * (BMM + BNM) * SST * 4;          // 36864
    const int tc_smem  = TC_STAGES * 32768 + 2048 + 1024;    // 101376
    static int attr_done = 0;
    static cudaStream_t s2 = nullptr;
    static cudaEvent_t evF = nullptr, evR = nullptr, evM1 = nullptr, evM2 = nullptr;
    if (!attr_done) {
        cudaFuncSetAttribute(gemm_mod_kernel, cudaFuncAttributeMaxDynamicSharedMemorySize, mod_smem);
        cudaFuncSetAttribute(tc_fp16_kernel<1>, cudaFuncAttributeMaxDynamicSharedMemorySize, tc_smem);
        cudaFuncSetAttribute(tc_fp16_kernel<2>, cudaFuncAttributeMaxDynamicSharedMemorySize, tc_smem);
        cudaStreamCreateWithFlags(&s2, cudaStreamNonBlocking);
        cudaEventCreateWithFlags(&evF,  cudaEventDisableTiming);
        cudaEventCreateWithFlags(&evR,  cudaEventDisableTiming);
        cudaEventCreateWithFlags(&evM1, cudaEventDisableTiming);
        cudaEventCreateWithFlags(&evM2, cudaEventDisableTiming);
        attr_done = 1;
    }

    // ---- proper capture fork: s2 must first wait on an event from stream 0 ----
    cudaEventRecord(evF, 0);
    cudaStreamWaitEvent(s2, evF, 0);

    // stream 0: critical path.  s2: siren prep (only needed by GEMM1).
    prep_crit_kernel<<<1600, 256>>>(mv0, mg0, mv1, mg1, mv2, mg2, X);
    prep_rest_kernel<<<1124, 256, 0, s2>>>(sv1, sg1, sv2, sg2, dv, dg, sv0, sg0, sb0);
    cudaEventRecord(evR, s2);

    // mod chain on stream 0 (64x64 tiles, 128 CTAs each)
    {
        dim3 grid(512 / BNM, NS / BMM);     // (8, 16)
        gemm_mod_kernel<<<grid, 256, mod_smem>>>(Xr, wmod0, mb0, M0, Z0, INCH);
        gemm_mod_kernel<<<grid, 256, mod_smem>>>(Z0, wmod1, mb1, M1, Z1, KCAT);
        cudaEventRecord(evM1, 0);
        // fork: mod2 on s2 (serialized after prep_rest there; waits mod1)
        cudaStreamWaitEvent(s2, evM1, 0);
        gemm_mod_kernel<<<grid, 256, mod_smem, s2>>>(Z1, wmod2, mb2, M2, nullptr, KCAT);
        cudaEventRecord(evM2, s2);
    }

    // zero decoder accumulator, then GEMM1 (needs prep_rest results)
    cudaMemsetAsync(dir, 0, (size_t)ROWS * 3 * sizeof(float), 0);
    cudaStreamWaitEvent(0, evR, 0);
    {
        dim3 grid(512 / 128, ROWS / 128);
        tc_fp16_kernel<1><<<grid, 256, tc_smem>>>(nullptr, hW1, sb1, M1, M0, hHB);
        cudaStreamWaitEvent(0, evM2, 0);
        tc_fp16_kernel<2><<<grid, 256, tc_smem>>>(hHB, hW2, sb2, M2, nullptr, nullptr);
    }

    // cumsum (stream 0)
    cumsum_kernel<<<(NS * 3 + 255) / 256, 256>>>(out, db);
    (void)in_sizes; (void)n_in; (void)out_size;
}

// round 14
// speedup vs baseline: 1.3136x; 1.0001x over previous
#include <cuda_runtime.h>
#include <cuda_fp16.h>
#include <cstdint>

// ---------------- problem constants ----------------
#define NS      1024
#define NV      99
#define ROWS    (NS*NV)       // 101376
#define INCH    64
#define MH      512
#define SH      512
#define KCAT    (INCH+MH)     // 576
#define SCALE0  30.0f

// ---------------- device scratch ----------------
__device__ __half g_hW1[SH*SH];
__device__ __half g_hW2[SH*SH];
__device__ float  g_wdec[3*SH];
__device__ float  g_s0[NV*SH];
__device__ float  g_M0[NS*MH];
__device__ float  g_M1[NS*MH];
__device__ float  g_M2[NS*MH];
__device__ float  g_Z0[NS*KCAT];
__device__ float  g_Z1[NS*KCAT];
__device__ __half g_hHB[(size_t)ROWS*SH];
__device__ float  g_dir8[(size_t)ROWS*24];   // 8 partials x 3 dims per row

__device__ __forceinline__ float rna_tf32(float x){
    float y; asm("cvt.rna.tf32.f32 %0, %1;" : "=f"(y) : "f"(x)); return y;
}
__device__ __forceinline__ void cp16(uint32_t s, const void* g){
    asm volatile("cp.async.cg.shared.global [%0], [%1], 16;" :: "r"(s), "l"(g));
}
__device__ __forceinline__ void ldsm4(uint32_t& r0, uint32_t& r1, uint32_t& r2, uint32_t& r3,
                                      uint32_t addr){
    asm volatile("ldmatrix.sync.aligned.m8n8.x4.shared.b16 {%0,%1,%2,%3}, [%4];"
                 : "=r"(r0), "=r"(r1), "=r"(r2), "=r"(r3) : "r"(addr));
}

// ---------------- shared rownorm body ----------------
__device__ __forceinline__ void rownorm_row(const float* __restrict__ v,
                                            const float* __restrict__ g,
                                            float* o32, __half* o16,
                                            int cols, int r, int mode, int tid,
                                            float* red)
{
    const float* vr = v + (size_t)r * cols;
    float ss = 0.f;
    for (int c = tid; c < cols; c += 256) { float x = vr[c]; ss += x * x; }
    red[tid] = ss; __syncthreads();
    for (int s = 128; s > 0; s >>= 1) {
        if (tid < s) red[tid] += red[tid + s];
        __syncthreads();
    }
    float scale = g[r] * rsqrtf(red[0]);
    for (int c = tid; c < cols; c += 256) {
        float w = vr[c] * scale;
        if (mode == 2)      o16[(size_t)r * cols + c] = __float2half(w);
        else                o32[(size_t)r * cols + c] = w;
    }
}

// ================= zfill: Z prefix = rna(X) (side stream, tiny) =================
__global__ void zfill_kernel(const float* __restrict__ X)
{
    int i = blockIdx.x * 256 + threadIdx.x;    // 0..65535
    float v = rna_tf32(X[i]);
    int s = i >> 6, c = i & 63;
    g_Z0[(size_t)s * KCAT + c] = v;
    g_Z1[(size_t)s * KCAT + c] = v;
}

// ================= prep_rest: siren weight-norms + s0 table (off critical path) ==
__global__ void prep_rest_kernel(const float* __restrict__ sv1, const float* __restrict__ sg1,
                                 const float* __restrict__ sv2, const float* __restrict__ sg2,
                                 const float* __restrict__ dv,  const float* __restrict__ dg,
                                 const float* __restrict__ sv0, const float* __restrict__ sg0,
                                 const float* __restrict__ sb0)
{
    __shared__ float red[256];
    int b = blockIdx.x, tid = threadIdx.x;
    if (b < 1025) {
        if      (b < 512)  rownorm_row(sv1, sg1, nullptr, g_hW1, SH, b,       2, tid, red);
        else if (b < 1024) rownorm_row(sv2, sg2, nullptr, g_hW2, SH, b - 512, 2, tid, red);
        else {
            for (int r = 0; r < 3; r++) rownorm_row(dv, dg, g_wdec, nullptr, SH, r, 0, tid, red);
        }
    } else {                            // s0 table: 99 blocks
        int p = b - 1025;
        float t = (float)p / 99.f;
        for (int j = tid; j < SH; j += 256) {
            float vv = sv0[j];
            float w  = sg0[j] * vv * rsqrtf(vv * vv);
            g_s0[p * SH + j] = sinf(SCALE0 * (t * w + sb0[j]));
        }
    }
}

// ================= mod GEMM: raw weights, fused weight-norm in epilogue ==========
// out[row,col] = silu( scale[col]*acc + bias[col] ),  scale = g[col]/||v[col,:]||
#define BMM 64
#define BNM 64
#define BKM 32
#define SST 36
#define MOD_STAGES 4
__global__ __launch_bounds__(256, 2)
void gemm_mod_kernel(const float* __restrict__ A, const float* __restrict__ V,
                     const float* __restrict__ gvec, const float* __restrict__ bias,
                     float* __restrict__ out, float* __restrict__ zout, int K)
{
    extern __shared__ float sm[];
    float* sA = sm;
    float* sB = sm + MOD_STAGES * BMM * SST;
    const int tid = threadIdx.x;
    const int rowBase = blockIdx.y * BMM;
    const int colBase = blockIdx.x * BNM;
    const uint32_t sA_u = (uint32_t)__cvta_generic_to_shared(sA);
    const uint32_t sB_u = (uint32_t)__cvta_generic_to_shared(sB);
    const int lane = tid & 31, warp = tid >> 5;
    const int wm = warp & 3, wn = warp >> 2;         // warp tile 16 x 32
    const int gg = lane >> 2, tt = lane & 3;
    float acc[4][4] = {};
    float ss[4] = {0.f, 0.f, 0.f, 0.f};
    const int nk = K / BKM;

    auto load_stage = [&](int i, int buf){
        int k0 = i * BKM;
        #pragma unroll
        for (int it = 0; it < 2; it++){
            int c  = tid + it * 256;
            int r  = c >> 3;
            int kc = (c & 7) * 4;
            cp16(sA_u + (uint32_t)((buf * BMM * SST + r * SST + kc) * 4),
                 &A[(size_t)(rowBase + r) * K + k0 + kc]);
            cp16(sB_u + (uint32_t)((buf * BNM * SST + r * SST + kc) * 4),
                 &V[(size_t)(colBase + r) * K + k0 + kc]);
        }
        asm volatile("cp.async.commit_group;");
    };

    for (int s = 0; s < (nk < 3 ? nk : 3); s++) load_stage(s, s);

    for (int i = 0; i < nk; i++){
        if      (i + 3 <= nk) asm volatile("cp.async.wait_group 2;" ::: "memory");
        else if (i + 2 <= nk) asm volatile("cp.async.wait_group 1;" ::: "memory");
        else                  asm volatile("cp.async.wait_group 0;" ::: "memory");
        __syncthreads();
        const float* cA = sA + (i % MOD_STAGES) * BMM * SST;
        const float* cB = sB + (i % MOD_STAGES) * BNM * SST;
        #pragma unroll
        for (int kk = 0; kk < BKM; kk += 8){
            uint32_t a[4], b[4][2];
            {
                int r = wm * 16 + gg;
                a[0] = __float_as_uint(rna_tf32(cA[r * SST + kk + tt]));
                a[1] = __float_as_uint(rna_tf32(cA[(r + 8) * SST + kk + tt]));
                a[2] = __float_as_uint(rna_tf32(cA[r * SST + kk + tt + 4]));
                a[3] = __float_as_uint(rna_tf32(cA[(r + 8) * SST + kk + tt + 4]));
            }
            #pragma unroll
            for (int ni = 0; ni < 4; ni++){
                int c = wn * 32 + ni * 8 + gg;
                float bf0 = cB[c * SST + kk + tt];
                float bf1 = cB[c * SST + kk + tt + 4];
                ss[ni] = fmaf(bf0, bf0, ss[ni]);
                ss[ni] = fmaf(bf1, bf1, ss[ni]);
                b[ni][0] = __float_as_uint(rna_tf32(bf0));
                b[ni][1] = __float_as_uint(rna_tf32(bf1));
            }
            #pragma unroll
            for (int ni = 0; ni < 4; ni++){
                float* d = acc[ni];
                asm volatile(
                    "mma.sync.aligned.m16n8k8.row.col.f32.tf32.tf32.f32 "
                    "{%0,%1,%2,%3}, {%4,%5,%6,%7}, {%8,%9}, {%0,%1,%2,%3};"
                    : "+f"(d[0]), "+f"(d[1]), "+f"(d[2]), "+f"(d[3])
                    : "r"(a[0]), "r"(a[1]), "r"(a[2]), "r"(a[3]),
                      "r"(b[ni][0]), "r"(b[ni][1]));
            }
        }
        __syncthreads();
        if (i + 3 < nk) load_stage(i + 3, (i + 3) % MOD_STAGES);
    }

    // sumsq quad reduce: all 4 lanes of each quad hold the col (ni*8+gg) total
    #pragma unroll
    for (int ni = 0; ni < 4; ni++){
        ss[ni] += __shfl_xor_sync(0xFFFFFFFFu, ss[ni], 1);
        ss[ni] += __shfl_xor_sync(0xFFFFFFFFu, ss[ni], 2);
    }

    int row0 = rowBase + wm * 16 + gg;
    #pragma unroll
    for (int ni = 0; ni < 4; ni++){
        int col = colBase + wn * 32 + ni * 8 + tt * 2;
        float s0 = __shfl_sync(0xFFFFFFFFu, ss[ni], tt * 8);        // gg = 2tt quad
        float s1 = __shfl_sync(0xFFFFFFFFu, ss[ni], tt * 8 + 4);    // gg = 2tt+1 quad
        float sc0 = gvec[col]     * rsqrtf(s0);
        float sc1 = gvec[col + 1] * rsqrtf(s1);
        float b0 = bias[col], b1 = bias[col + 1];
        #pragma unroll
        for (int h = 0; h < 2; h++){
            int row = row0 + h * 8;
            float v0 = acc[ni][h * 2 + 0] * sc0 + b0;
            float v1 = acc[ni][h * 2 + 1] * sc1 + b1;
            v0 = v0 / (1.f + __expf(-v0));
            v1 = v1 / (1.f + __expf(-v1));
            *reinterpret_cast<float2*>(&out[(size_t)row * 512 + col]) = make_float2(v0, v1);
            if (zout)
                *reinterpret_cast<float2*>(&zout[(size_t)row * KCAT + 64 + col]) =
                    make_float2(rna_tf32(v0), rna_tf32(v1));
        }
    }
}

// ================= fp16 tensor-core GEMM (101376 x 512 x 512), 3-stage pipeline ==
// MODE 1: A produced on the fly = half((1-gateA)*s0); stores half (1-gateE)*sin.
// MODE 2: A loaded half; decoder partials -> g_dir8 (per-warp slot, race-free).
#define BK2 64
#define TC_STAGES 3

template<int MODE>
__global__ __launch_bounds__(256, 2)
void tc_fp16_kernel(const __half* __restrict__ A, const __half* __restrict__ W,
                    const float* __restrict__ bias, const float* __restrict__ gateE,
                    const float* __restrict__ gateA, __half* __restrict__ out)
{
    extern __shared__ __align__(1024) char smem_raw[];
    uint32_t base  = (uint32_t)__cvta_generic_to_shared(smem_raw);
    uint32_t abase = (base + 1023u) & ~1023u;
    const int tid = threadIdx.x, warp = tid >> 5, lane = tid & 31;
    const int rowBase = blockIdx.y * 128, colBase = blockIdx.x * 128;
    const int wm = warp & 3, wn = warp >> 2;
    const int gl = (lane >> 3) & 1, gh = lane >> 4, lr = lane & 7;

    float* wds = reinterpret_cast<float*>(smem_raw + (abase - base) + TC_STAGES * 32768);
    if (MODE == 2 && tid < 128) {
        #pragma unroll
        for (int d = 0; d < 3; d++)
            wds[d * 128 + tid] = g_wdec[d * 512 + colBase + tid];
    }

    auto load_B = [&](int t, int buf){
        uint32_t bBuf = abase + buf * 32768 + 16384;
        int k0 = t * BK2;
        #pragma unroll
        for (int it = 0; it < 4; it++){
            int idx = tid + it * 256;
            int r = idx >> 3, c = idx & 7;
            uint32_t off = (uint32_t)(r * 128 + ((c ^ (r & 7)) * 16));
            cp16(bBuf + off, &W[(size_t)(colBase + r) * 512 + k0 + c * 8]);
        }
    };
    auto load_A = [&](int t, int buf){
        uint32_t aBuf = abase + buf * 32768;
        int k0 = t * BK2;
        #pragma unroll
        for (int it = 0; it < 4; it++){
            int idx = tid + it * 256;
            int r = idx >> 3, c = idx & 7;
            uint32_t off = (uint32_t)(r * 128 + ((c ^ (r & 7)) * 16));
            cp16(aBuf + off, &A[(size_t)(rowBase + r) * 512 + k0 + c * 8]);
        }
    };
    auto produce_A = [&](int t, int buf){
        uint32_t aBuf = abase + buf * 32768;
        int k0 = t * BK2;
        #pragma unroll
        for (int it = 0; it < 4; it++){
            int idx = tid + it * 256;
            int r = idx >> 3, c = idx & 7;
            int row = rowBase + r;
            int strand = row / NV, p = row - strand * NV;
            const float4* m4 = reinterpret_cast<const float4*>(&gateA[(size_t)strand * MH + k0 + c * 8]);
            const float4* s4 = reinterpret_cast<const float4*>(&g_s0[p * SH + k0 + c * 8]);
            float4 m0 = m4[0], m1 = m4[1], s0v = s4[0], s1v = s4[1];
            __half2 h0 = __floats2half2_rn((1.f - m0.x) * s0v.x, (1.f - m0.y) * s0v.y);
            __half2 h1 = __floats2half2_rn((1.f - m0.z) * s0v.z, (1.f - m0.w) * s0v.w);
            __half2 h2 = __floats2half2_rn((1.f - m1.x) * s1v.x, (1.f - m1.y) * s1v.y);
            __half2 h3 = __floats2half2_rn((1.f - m1.z) * s1v.z, (1.f - m1.w) * s1v.w);
            uint32_t off = (uint32_t)(r * 128 + ((c ^ (r & 7)) * 16));
            asm volatile("st.shared.v4.b32 [%0], {%1,%2,%3,%4};"
                         :: "r"(aBuf + off),
                            "r"(*reinterpret_cast<uint32_t*>(&h0)),
                            "r"(*reinterpret_cast<uint32_t*>(&h1)),
                            "r"(*reinterpret_cast<uint32_t*>(&h2)),
                            "r"(*reinterpret_cast<uint32_t*>(&h3)) : "memory");
        }
    };
    auto load_stage = [&](int t, int buf){
        if (MODE == 1) produce_A(t, buf); else load_A(t, buf);
        load_B(t, buf);
        asm volatile("cp.async.commit_group;");
    };

    float acc[2][8][4] = {};

    load_stage(0, 0);
    load_stage(1, 1);
    load_stage(2, 2);

    for (int t = 0; t < 8; t++){
        if (t < 7) asm volatile("cp.async.wait_group 2;" ::: "memory");
        else       asm volatile("cp.async.wait_group 0;" ::: "memory");
        __syncthreads();
        int buf = t % TC_STAGES;
        uint32_t aBuf = abase + buf * 32768;
        uint32_t bBuf = aBuf + 16384;

        #pragma unroll
        for (int kk = 0; kk < 4; kk++){
            int kc = kk * 2 + gh;
            uint32_t a[2][4], b[4][4];
            #pragma unroll
            for (int mi = 0; mi < 2; mi++){
                int row = wm * 32 + mi * 16 + gl * 8 + lr;
                ldsm4(a[mi][0], a[mi][1], a[mi][2], a[mi][3],
                      aBuf + (uint32_t)(row * 128 + ((kc ^ lr) * 16)));
            }
            #pragma unroll
            for (int nq = 0; nq < 4; nq++){
                int nrow = wn * 64 + nq * 16 + gl * 8 + lr;
                ldsm4(b[nq][0], b[nq][1], b[nq][2], b[nq][3],
                      bBuf + (uint32_t)(nrow * 128 + ((kc ^ lr) * 16)));
            }
            #pragma unroll
            for (int mi = 0; mi < 2; mi++)
                #pragma unroll
                for (int nq = 0; nq < 4; nq++){
                    #pragma unroll
                    for (int hf = 0; hf < 2; hf++){
                        float* d = acc[mi][nq * 2 + hf];
                        asm volatile(
                            "mma.sync.aligned.m16n8k16.row.col.f32.f16.f16.f32 "
                            "{%0,%1,%2,%3}, {%4,%5,%6,%7}, {%8,%9}, {%0,%1,%2,%3};"
                            : "+f"(d[0]), "+f"(d[1]), "+f"(d[2]), "+f"(d[3])
                            : "r"(a[mi][0]), "r"(a[mi][1]), "r"(a[mi][2]), "r"(a[mi][3]),
                              "r"(b[nq][hf]), "r"(b[nq][2 + hf]));
                    }
                }
        }
        __syncthreads();
        if (t + 3 < 8) load_stage(t + 3, (t + 3) % TC_STAGES);
    }

    // ---- epilogue ----
    const int gg = lane >> 2, tt = lane & 3;
    float p3[4][3];
    if (MODE == 2){
        #pragma unroll
        for (int q = 0; q < 4; q++){ p3[q][0] = 0.f; p3[q][1] = 0.f; p3[q][2] = 0.f; }
    }
    #pragma unroll
    for (int mi = 0; mi < 2; mi++){
        int row0 = rowBase + wm * 32 + mi * 16 + gg;
        #pragma unroll
        for (int ni = 0; ni < 8; ni++){
            int col = colBase + wn * 64 + ni * 8 + tt * 2;
            float b0 = bias[col], b1 = bias[col + 1];
            #pragma unroll
            for (int h = 0; h < 2; h++){
                int row = row0 + h * 8;
                int strand = row / NV;
                float g0 = 1.f - gateE[(size_t)strand * MH + col];
                float g1 = 1.f - gateE[(size_t)strand * MH + col + 1];
                float v0 = g0 * __sinf(acc[mi][ni][h * 2 + 0] + b0);
                float v1 = g1 * __sinf(acc[mi][ni][h * 2 + 1] + b1);
                if (MODE == 1){
                    *reinterpret_cast<__half2*>(&out[(size_t)row * 512 + col]) =
                        __floats2half2_rn(v0, v1);
                } else {
                    int lc = col - colBase;
                    int q = mi * 2 + h;
                    #pragma unroll
                    for (int d = 0; d < 3; d++)
                        p3[q][d] += v0 * wds[d * 128 + lc] + v1 * wds[d * 128 + lc + 1];
                }
            }
        }
    }
    if (MODE == 2){
        #pragma unroll
        for (int q = 0; q < 4; q++)
            #pragma unroll
            for (int d = 0; d < 3; d++){
                float v = p3[q][d];
                v += __shfl_xor_sync(0xFFFFFFFFu, v, 1);
                v += __shfl_xor_sync(0xFFFFFFFFu, v, 2);
                p3[q][d] = v;
            }
        if (tt == 0){
            // per (column-CTA, wn) slot: 8 partials per row, race-free
            int slot = blockIdx.x * 2 + wn;
            int rb = rowBase + wm * 32 + gg;
            #pragma unroll
            for (int q = 0; q < 4; q++){
                int row = rb + (q & 1) * 8 + (q >> 1) * 16;
                #pragma unroll
                for (int d = 0; d < 3; d++)
                    g_dir8[(size_t)row * 24 + slot * 3 + d] = p3[q][d] * 0.01f;
            }
        }
    }
}

// ================= cumsum: warp per strand, shfl inclusive scan =================
__global__ void cumsum_kernel(float* __restrict__ out, const float* __restrict__ bd)
{
    int gw = (blockIdx.x * blockDim.x + threadIdx.x) >> 5;   // strand
    int lane = threadIdx.x & 31;
    if (gw >= NS) return;
    int s = gw;
    float bias0 = bd[0] * 0.01f, bias1 = bd[1] * 0.01f, bias2 = bd[2] * 0.01f;
    if (lane < 3) out[(size_t)s * 300 + lane] = 0.f;
    float c0 = 0.f, c1 = 0.f, c2 = 0.f;
    #pragma unroll
    for (int ch = 0; ch < 4; ch++){
        int p = ch * 32 + lane;
        float v0 = 0.f, v1 = 0.f, v2 = 0.f;
        if (p < NV){
            const float* b = &g_dir8[(size_t)(s * NV + p) * 24];
            #pragma unroll
            for (int j = 0; j < 8; j++){
                v0 += b[j * 3 + 0];
                v1 += b[j * 3 + 1];
                v2 += b[j * 3 + 2];
            }
            v0 += bias0; v1 += bias1; v2 += bias2;
        }
        #pragma unroll
        for (int o = 1; o < 32; o <<= 1){
            float t0 = __shfl_up_sync(0xFFFFFFFFu, v0, o);
            float t1 = __shfl_up_sync(0xFFFFFFFFu, v1, o);
            float t2 = __shfl_up_sync(0xFFFFFFFFu, v2, o);
            if (lane >= o){ v0 += t0; v1 += t1; v2 += t2; }
        }
        v0 += c0; v1 += c1; v2 += c2;
        if (p < NV){
            float* ob = out + (size_t)s * 300 + (size_t)(p + 1) * 3;
            ob[0] = v0; ob[1] = v1; ob[2] = v2;
        }
        c0 = __shfl_sync(0xFFFFFFFFu, v0, 31);
        c1 = __shfl_sync(0xFFFFFFFFu, v1, 31);
        c2 = __shfl_sync(0xFFFFFFFFu, v2, 31);
    }
}

// ================= host launch =================
static void* sym(const void* s) { void* p = nullptr; cudaGetSymbolAddress(&p, s); return p; }

extern "C" void kernel_launch(void* const* d_in, const int* in_sizes, int n_in,
                              void* d_out, int out_size)
{
    const float* X   = (const float*)d_in[0];
    const float* mv0 = (const float*)d_in[1];  const float* mg0 = (const float*)d_in[2];  const float* mb0 = (const float*)d_in[3];
    const float* mv1 = (const float*)d_in[4];  const float* mg1 = (const float*)d_in[5];  const float* mb1 = (const float*)d_in[6];
    const float* mv2 = (const float*)d_in[7];  const float* mg2 = (const float*)d_in[8];  const float* mb2 = (const float*)d_in[9];
    const float* sv0 = (const float*)d_in[10]; const float* sg0 = (const float*)d_in[11]; const float* sb0 = (const float*)d_in[12];
    const float* sv1 = (const float*)d_in[13]; const float* sg1 = (const float*)d_in[14]; const float* sb1 = (const float*)d_in[15];
    const float* sv2 = (const float*)d_in[16]; const float* sg2 = (const float*)d_in[17]; const float* sb2 = (const float*)d_in[18];
    const float* dv  = (const float*)d_in[19]; const float* dg  = (const float*)d_in[20]; const float* db  = (const float*)d_in[21];
    float* out = (float*)d_out;

    __half* hW1 = (__half*)sym(g_hW1);
    __half* hW2 = (__half*)sym(g_hW2);
    float*  M0  = (float*)sym(g_M0);
    float*  M1  = (float*)sym(g_M1);
    float*  M2  = (float*)sym(g_M2);
    float*  Z0  = (float*)sym(g_Z0);
    float*  Z1  = (float*)sym(g_Z1);
    __half* hHB = (__half*)sym(g_hHB);

    const int mod_smem = MOD_STAGES * 2 * BMM * SST * 4;     // 73728
    const int tc_smem  = TC_STAGES * 32768 + 2048 + 1024;    // 101376
    static int attr_done = 0;
    static cudaStream_t s2 = nullptr;
    static cudaEvent_t evF = nullptr, evZ = nullptr, evR = nullptr, evM1 = nullptr, evM2 = nullptr;
    if (!attr_done) {
        cudaFuncSetAttribute(gemm_mod_kernel, cudaFuncAttributeMaxDynamicSharedMemorySize, mod_smem);
        cudaFuncSetAttribute(tc_fp16_kernel<1>, cudaFuncAttributeMaxDynamicSharedMemorySize, tc_smem);
        cudaFuncSetAttribute(tc_fp16_kernel<2>, cudaFuncAttributeMaxDynamicSharedMemorySize, tc_smem);
        cudaStreamCreateWithFlags(&s2, cudaStreamNonBlocking);
        cudaEventCreateWithFlags(&evF,  cudaEventDisableTiming);
        cudaEventCreateWithFlags(&evZ,  cudaEventDisableTiming);
        cudaEventCreateWithFlags(&evR,  cudaEventDisableTiming);
        cudaEventCreateWithFlags(&evM1, cudaEventDisableTiming);
        cudaEventCreateWithFlags(&evM2, cudaEventDisableTiming);
        attr_done = 1;
    }

    // ---- capture fork: s2 must first wait on an event from stream 0 ----
    cudaEventRecord(evF, 0);
    cudaStreamWaitEvent(s2, evF, 0);

    // s2: Z prefix fill (needed by mod1), then siren prep (needed by GEMM1)
    zfill_kernel<<<256, 256, 0, s2>>>(X);
    cudaEventRecord(evZ, s2);
    prep_rest_kernel<<<1124, 256, 0, s2>>>(sv1, sg1, sv2, sg2, dv, dg, sv0, sg0, sb0);
    cudaEventRecord(evR, s2);

    // stream 0: mod chain with fused weight-norm (raw v weights, no prep!)
    {
        dim3 grid(512 / BNM, NS / BMM);     // (8, 16) = 128 CTAs
        gemm_mod_kernel<<<grid, 256, mod_smem>>>(X, mv0, mg0, mb0, M0, Z0, INCH);
        cudaStreamWaitEvent(0, evZ, 0);
        gemm_mod_kernel<<<grid, 256, mod_smem>>>(Z0, mv1, mg1, mb1, M1, Z1, KCAT);
        cudaEventRecord(evM1, 0);
        // mod2 on s2 (after prep_rest there; waits mod1)
        cudaStreamWaitEvent(s2, evM1, 0);
        gemm_mod_kernel<<<grid, 256, mod_smem, s2>>>(Z1, mv2, mg2, mb2, M2, nullptr, KCAT);
        cudaEventRecord(evM2, s2);
    }

    // GEMM1 (needs prep_rest + M0 + M1), then GEMM2 (needs M2)
    cudaStreamWaitEvent(0, evR, 0);
    {
        dim3 grid(512 / 128, ROWS / 128);
        tc_fp16_kernel<1><<<grid, 256, tc_smem>>>(nullptr, hW1, sb1, M1, M0, hHB);
        cudaStreamWaitEvent(0, evM2, 0);
        tc_fp16_kernel<2><<<grid, 256, tc_smem>>>(hHB, hW2, sb2, M2, nullptr, nullptr);
    }

    // cumsum: warp-per-strand scan over decoder partials
    cumsum_kernel<<<(NS * 32 + 255) / 256, 256>>>(out, db);
    (void)in_sizes; (void)n_in; (void)out_size;
}

// round 15
// speedup vs baseline: 1.5330x; 1.1670x over previous
#include <cuda_runtime.h>
#include <cuda_fp16.h>
#include <cstdint>

// ---------------- problem constants ----------------
#define NS      1024
#define NV      99
#define ROWS    (NS*NV)       // 101376
#define INCH    64
#define MH      512
#define SH      512
#define KCAT    (INCH+MH)     // 576
#define SCALE0  30.0f

// ---------------- device scratch ----------------
__device__ __half g_hW1[SH*SH];
__device__ __half g_hW2[SH*SH];
__device__ float  g_wdec[3*SH];
__device__ __half g_s0h[NV*SH];              // half(s0)
__device__ __half g_gc0[NS*MH];              // half(1 - M0)
__device__ float  g_M1[NS*MH];
__device__ float  g_M2[NS*MH];
__device__ float  g_Z0[NS*KCAT];
__device__ float  g_Z1[NS*KCAT];
__device__ __half g_hHB[(size_t)ROWS*SH];
__device__ float  g_dir8[(size_t)ROWS*24];   // 8 partials x 3 dims per row

__device__ __forceinline__ float rna_tf32(float x){
    float y; asm("cvt.rna.tf32.f32 %0, %1;" : "=f"(y) : "f"(x)); return y;
}
__device__ __forceinline__ void cp16(uint32_t s, const void* g){
    asm volatile("cp.async.cg.shared.global [%0], [%1], 16;" :: "r"(s), "l"(g));
}
__device__ __forceinline__ void ldsm4(uint32_t& r0, uint32_t& r1, uint32_t& r2, uint32_t& r3,
                                      uint32_t addr){
    asm volatile("ldmatrix.sync.aligned.m8n8.x4.shared.b16 {%0,%1,%2,%3}, [%4];"
                 : "=r"(r0), "=r"(r1), "=r"(r2), "=r"(r3) : "r"(addr));
}

// ---------------- shared rownorm body ----------------
__device__ __forceinline__ void rownorm_row(const float* __restrict__ v,
                                            const float* __restrict__ g,
                                            float* o32, __half* o16,
                                            int cols, int r, int mode, int tid,
                                            float* red)
{
    const float* vr = v + (size_t)r * cols;
    float ss = 0.f;
    for (int c = tid; c < cols; c += 256) { float x = vr[c]; ss += x * x; }
    red[tid] = ss; __syncthreads();
    for (int s = 128; s > 0; s >>= 1) {
        if (tid < s) red[tid] += red[tid + s];
        __syncthreads();
    }
    float scale = g[r] * rsqrtf(red[0]);
    for (int c = tid; c < cols; c += 256) {
        float w = vr[c] * scale;
        if (mode == 2)      o16[(size_t)r * cols + c] = __float2half(w);
        else                o32[(size_t)r * cols + c] = w;
    }
}

// ================= zfill: Z prefix = rna(X) (side stream, tiny) =================
__global__ void zfill_kernel(const float* __restrict__ X)
{
    int i = blockIdx.x * 256 + threadIdx.x;    // 0..65535
    float v = rna_tf32(X[i]);
    int s = i >> 6, c = i & 63;
    g_Z0[(size_t)s * KCAT + c] = v;
    g_Z1[(size_t)s * KCAT + c] = v;
}

// ================= prep_rest: siren weight-norms + s0 table (off critical path) ==
__global__ void prep_rest_kernel(const float* __restrict__ sv1, const float* __restrict__ sg1,
                                 const float* __restrict__ sv2, const float* __restrict__ sg2,
                                 const float* __restrict__ dv,  const float* __restrict__ dg,
                                 const float* __restrict__ sv0, const float* __restrict__ sg0,
                                 const float* __restrict__ sb0)
{
    __shared__ float red[256];
    int b = blockIdx.x, tid = threadIdx.x;
    if (b < 1025) {
        if      (b < 512)  rownorm_row(sv1, sg1, nullptr, g_hW1, SH, b,       2, tid, red);
        else if (b < 1024) rownorm_row(sv2, sg2, nullptr, g_hW2, SH, b - 512, 2, tid, red);
        else {
            for (int r = 0; r < 3; r++) rownorm_row(dv, dg, g_wdec, nullptr, SH, r, 0, tid, red);
        }
    } else {                            // s0 table (half): 99 blocks
        int p = b - 1025;
        float t = (float)p / 99.f;
        for (int j = tid; j < SH; j += 256) {
            float vv = sv0[j];
            float w  = sg0[j] * vv * rsqrtf(vv * vv);
            g_s0h[p * SH + j] = __float2half(sinf(SCALE0 * (t * w + sb0[j])));
        }
    }
}

// ================= mod GEMM: raw weights, fused weight-norm in epilogue ==========
// out(optional fp32) = silu(scale*acc+bias); hcout(optional) = half(1 - silu(...))
#define BMM 64
#define BNM 64
#define BKM 32
#define SST 36
#define MOD_STAGES 4
__global__ __launch_bounds__(256, 2)
void gemm_mod_kernel(const float* __restrict__ A, const float* __restrict__ V,
                     const float* __restrict__ gvec, const float* __restrict__ bias,
                     float* __restrict__ out, float* __restrict__ zout,
                     __half* __restrict__ hcout, int K)
{
    extern __shared__ float sm[];
    float* sA = sm;
    float* sB = sm + MOD_STAGES * BMM * SST;
    const int tid = threadIdx.x;
    const int rowBase = blockIdx.y * BMM;
    const int colBase = blockIdx.x * BNM;
    const uint32_t sA_u = (uint32_t)__cvta_generic_to_shared(sA);
    const uint32_t sB_u = (uint32_t)__cvta_generic_to_shared(sB);
    const int lane = tid & 31, warp = tid >> 5;
    const int wm = warp & 3, wn = warp >> 2;         // warp tile 16 x 32
    const int gg = lane >> 2, tt = lane & 3;
    float acc[4][4] = {};
    float ss[4] = {0.f, 0.f, 0.f, 0.f};
    const int nk = K / BKM;

    auto load_stage = [&](int i, int buf){
        int k0 = i * BKM;
        #pragma unroll
        for (int it = 0; it < 2; it++){
            int c  = tid + it * 256;
            int r  = c >> 3;
            int kc = (c & 7) * 4;
            cp16(sA_u + (uint32_t)((buf * BMM * SST + r * SST + kc) * 4),
                 &A[(size_t)(rowBase + r) * K + k0 + kc]);
            cp16(sB_u + (uint32_t)((buf * BNM * SST + r * SST + kc) * 4),
                 &V[(size_t)(colBase + r) * K + k0 + kc]);
        }
        asm volatile("cp.async.commit_group;");
    };

    for (int s = 0; s < (nk < 3 ? nk : 3); s++) load_stage(s, s);

    for (int i = 0; i < nk; i++){
        if      (i + 3 <= nk) asm volatile("cp.async.wait_group 2;" ::: "memory");
        else if (i + 2 <= nk) asm volatile("cp.async.wait_group 1;" ::: "memory");
        else                  asm volatile("cp.async.wait_group 0;" ::: "memory");
        __syncthreads();
        const float* cA = sA + (i % MOD_STAGES) * BMM * SST;
        const float* cB = sB + (i % MOD_STAGES) * BNM * SST;
        #pragma unroll
        for (int kk = 0; kk < BKM; kk += 8){
            uint32_t a[4], b[4][2];
            {
                int r = wm * 16 + gg;
                a[0] = __float_as_uint(rna_tf32(cA[r * SST + kk + tt]));
                a[1] = __float_as_uint(rna_tf32(cA[(r + 8) * SST + kk + tt]));
                a[2] = __float_as_uint(rna_tf32(cA[r * SST + kk + tt + 4]));
                a[3] = __float_as_uint(rna_tf32(cA[(r + 8) * SST + kk + tt + 4]));
            }
            #pragma unroll
            for (int ni = 0; ni < 4; ni++){
                int c = wn * 32 + ni * 8 + gg;
                float bf0 = cB[c * SST + kk + tt];
                float bf1 = cB[c * SST + kk + tt + 4];
                ss[ni] = fmaf(bf0, bf0, ss[ni]);
                ss[ni] = fmaf(bf1, bf1, ss[ni]);
                b[ni][0] = __float_as_uint(rna_tf32(bf0));
                b[ni][1] = __float_as_uint(rna_tf32(bf1));
            }
            #pragma unroll
            for (int ni = 0; ni < 4; ni++){
                float* d = acc[ni];
                asm volatile(
                    "mma.sync.aligned.m16n8k8.row.col.f32.tf32.tf32.f32 "
                    "{%0,%1,%2,%3}, {%4,%5,%6,%7}, {%8,%9}, {%0,%1,%2,%3};"
                    : "+f"(d[0]), "+f"(d[1]), "+f"(d[2]), "+f"(d[3])
                    : "r"(a[0]), "r"(a[1]), "r"(a[2]), "r"(a[3]),
                      "r"(b[ni][0]), "r"(b[ni][1]));
            }
        }
        __syncthreads();
        if (i + 3 < nk) load_stage(i + 3, (i + 3) % MOD_STAGES);
    }

    // sumsq quad reduce: all 4 lanes of each quad hold the col (ni*8+gg) total
    #pragma unroll
    for (int ni = 0; ni < 4; ni++){
        ss[ni] += __shfl_xor_sync(0xFFFFFFFFu, ss[ni], 1);
        ss[ni] += __shfl_xor_sync(0xFFFFFFFFu, ss[ni], 2);
    }

    int row0 = rowBase + wm * 16 + gg;
    #pragma unroll
    for (int ni = 0; ni < 4; ni++){
        int col = colBase + wn * 32 + ni * 8 + tt * 2;
        float s0 = __shfl_sync(0xFFFFFFFFu, ss[ni], tt * 8);        // gg = 2tt quad
        float s1 = __shfl_sync(0xFFFFFFFFu, ss[ni], tt * 8 + 4);    // gg = 2tt+1 quad
        float sc0 = gvec[col]     * rsqrtf(s0);
        float sc1 = gvec[col + 1] * rsqrtf(s1);
        float b0 = bias[col], b1 = bias[col + 1];
        #pragma unroll
        for (int h = 0; h < 2; h++){
            int row = row0 + h * 8;
            float v0 = acc[ni][h * 2 + 0] * sc0 + b0;
            float v1 = acc[ni][h * 2 + 1] * sc1 + b1;
            v0 = v0 / (1.f + __expf(-v0));
            v1 = v1 / (1.f + __expf(-v1));
            if (out)
                *reinterpret_cast<float2*>(&out[(size_t)row * 512 + col]) = make_float2(v0, v1);
            if (hcout)
                *reinterpret_cast<__half2*>(&hcout[(size_t)row * 512 + col]) =
                    __floats2half2_rn(1.f - v0, 1.f - v1);
            if (zout)
                *reinterpret_cast<float2*>(&zout[(size_t)row * KCAT + 64 + col]) =
                    make_float2(rna_tf32(v0), rna_tf32(v1));
        }
    }
}

// ================= fp16 tensor-core GEMM (rows-chunked), 3-stage pipeline ========
// MODE 1: A produced on the fly = gc0(half) * s0h(half); stores half (1-gateE)*sin.
// MODE 2: A loaded half; decoder partials -> g_dir8 (per-warp slot, race-free).
#define BK2 64
#define TC_STAGES 3

template<int MODE>
__global__ __launch_bounds__(256, 2)
void tc_fp16_kernel(const __half* __restrict__ A, const __half* __restrict__ W,
                    const float* __restrict__ bias, const float* __restrict__ gateE,
                    __half* __restrict__ out, int rowOff)
{
    extern __shared__ __align__(1024) char smem_raw[];
    uint32_t base  = (uint32_t)__cvta_generic_to_shared(smem_raw);
    uint32_t abase = (base + 1023u) & ~1023u;
    const int tid = threadIdx.x, warp = tid >> 5, lane = tid & 31;
    const int rowBase = rowOff + blockIdx.y * 128, colBase = blockIdx.x * 128;
    const int wm = warp & 3, wn = warp >> 2;
    const int gl = (lane >> 3) & 1, gh = lane >> 4, lr = lane & 7;

    float* wds = reinterpret_cast<float*>(smem_raw + (abase - base) + TC_STAGES * 32768);
    if (MODE == 2 && tid < 128) {
        #pragma unroll
        for (int d = 0; d < 3; d++)
            wds[d * 128 + tid] = g_wdec[d * 512 + colBase + tid];
    }

    auto load_B = [&](int t, int buf){
        uint32_t bBuf = abase + buf * 32768 + 16384;
        int k0 = t * BK2;
        #pragma unroll
        for (int it = 0; it < 4; it++){
            int idx = tid + it * 256;
            int r = idx >> 3, c = idx & 7;
            uint32_t off = (uint32_t)(r * 128 + ((c ^ (r & 7)) * 16));
            cp16(bBuf + off, &W[(size_t)(colBase + r) * 512 + k0 + c * 8]);
        }
    };
    auto load_A = [&](int t, int buf){
        uint32_t aBuf = abase + buf * 32768;
        int k0 = t * BK2;
        #pragma unroll
        for (int it = 0; it < 4; it++){
            int idx = tid + it * 256;
            int r = idx >> 3, c = idx & 7;
            uint32_t off = (uint32_t)(r * 128 + ((c ^ (r & 7)) * 16));
            cp16(aBuf + off, &A[(size_t)(rowBase + r) * 512 + k0 + c * 8]);
        }
    };
    auto produce_A = [&](int t, int buf){     // MODE 1: gc0 * s0h (all-half path)
        uint32_t aBuf = abase + buf * 32768;
        int k0 = t * BK2;
        #pragma unroll
        for (int it = 0; it < 4; it++){
            int idx = tid + it * 256;
            int r = idx >> 3, c = idx & 7;
            int row = rowBase + r;
            int strand = row / NV, p = row - strand * NV;
            uint4 mv = *reinterpret_cast<const uint4*>(&g_gc0[(size_t)strand * MH + k0 + c * 8]);
            uint4 sv = *reinterpret_cast<const uint4*>(&g_s0h[p * SH + k0 + c * 8]);
            __half2 h0 = __hmul2(*reinterpret_cast<__half2*>(&mv.x), *reinterpret_cast<__half2*>(&sv.x));
            __half2 h1 = __hmul2(*reinterpret_cast<__half2*>(&mv.y), *reinterpret_cast<__half2*>(&sv.y));
            __half2 h2 = __hmul2(*reinterpret_cast<__half2*>(&mv.z), *reinterpret_cast<__half2*>(&sv.z));
            __half2 h3 = __hmul2(*reinterpret_cast<__half2*>(&mv.w), *reinterpret_cast<__half2*>(&sv.w));
            uint32_t off = (uint32_t)(r * 128 + ((c ^ (r & 7)) * 16));
            asm volatile("st.shared.v4.b32 [%0], {%1,%2,%3,%4};"
                         :: "r"(aBuf + off),
                            "r"(*reinterpret_cast<uint32_t*>(&h0)),
                            "r"(*reinterpret_cast<uint32_t*>(&h1)),
                            "r"(*reinterpret_cast<uint32_t*>(&h2)),
                            "r"(*reinterpret_cast<uint32_t*>(&h3)) : "memory");
        }
    };
    auto load_stage = [&](int t, int buf){
        if (MODE == 1) produce_A(t, buf); else load_A(t, buf);
        load_B(t, buf);
        asm volatile("cp.async.commit_group;");
    };

    float acc[2][8][4] = {};

    load_stage(0, 0);
    load_stage(1, 1);
    load_stage(2, 2);

    for (int t = 0; t < 8; t++){
        if (t < 7) asm volatile("cp.async.wait_group 2;" ::: "memory");
        else       asm volatile("cp.async.wait_group 0;" ::: "memory");
        __syncthreads();
        int buf = t % TC_STAGES;
        uint32_t aBuf = abase + buf * 32768;
        uint32_t bBuf = aBuf + 16384;

        #pragma unroll
        for (int kk = 0; kk < 4; kk++){
            int kc = kk * 2 + gh;
            uint32_t a[2][4], b[4][4];
            #pragma unroll
            for (int mi = 0; mi < 2; mi++){
                int row = wm * 32 + mi * 16 + gl * 8 + lr;
                ldsm4(a[mi][0], a[mi][1], a[mi][2], a[mi][3],
                      aBuf + (uint32_t)(row * 128 + ((kc ^ lr) * 16)));
            }
            #pragma unroll
            for (int nq = 0; nq < 4; nq++){
                int nrow = wn * 64 + nq * 16 + gl * 8 + lr;
                ldsm4(b[nq][0], b[nq][1], b[nq][2], b[nq][3],
                      bBuf + (uint32_t)(nrow * 128 + ((kc ^ lr) * 16)));
            }
            #pragma unroll
            for (int mi = 0; mi < 2; mi++)
                #pragma unroll
                for (int nq = 0; nq < 4; nq++){
                    #pragma unroll
                    for (int hf = 0; hf < 2; hf++){
                        float* d = acc[mi][nq * 2 + hf];
                        asm volatile(
                            "mma.sync.aligned.m16n8k16.row.col.f32.f16.f16.f32 "
                            "{%0,%1,%2,%3}, {%4,%5,%6,%7}, {%8,%9}, {%0,%1,%2,%3};"
                            : "+f"(d[0]), "+f"(d[1]), "+f"(d[2]), "+f"(d[3])
                            : "r"(a[mi][0]), "r"(a[mi][1]), "r"(a[mi][2]), "r"(a[mi][3]),
                              "r"(b[nq][hf]), "r"(b[nq][2 + hf]));
                    }
                }
        }
        __syncthreads();
        if (t + 3 < 8) load_stage(t + 3, (t + 3) % TC_STAGES);
    }

    // ---- epilogue ----
    const int gg = lane >> 2, tt = lane & 3;
    float p3[4][3];
    if (MODE == 2){
        #pragma unroll
        for (int q = 0; q < 4; q++){ p3[q][0] = 0.f; p3[q][1] = 0.f; p3[q][2] = 0.f; }
    }
    #pragma unroll
    for (int mi = 0; mi < 2; mi++){
        int row0 = rowBase + wm * 32 + mi * 16 + gg;
        #pragma unroll
        for (int ni = 0; ni < 8; ni++){
            int col = colBase + wn * 64 + ni * 8 + tt * 2;
            float b0 = bias[col], b1 = bias[col + 1];
            #pragma unroll
            for (int h = 0; h < 2; h++){
                int row = row0 + h * 8;
                int strand = row / NV;
                float g0 = 1.f - gateE[(size_t)strand * MH + col];
                float g1 = 1.f - gateE[(size_t)strand * MH + col + 1];
                float v0 = g0 * __sinf(acc[mi][ni][h * 2 + 0] + b0);
                float v1 = g1 * __sinf(acc[mi][ni][h * 2 + 1] + b1);
                if (MODE == 1){
                    *reinterpret_cast<__half2*>(&out[(size_t)row * 512 + col]) =
                        __floats2half2_rn(v0, v1);
                } else {
                    int lc = col - colBase;
                    int q = mi * 2 + h;
                    #pragma unroll
                    for (int d = 0; d < 3; d++)
                        p3[q][d] += v0 * wds[d * 128 + lc] + v1 * wds[d * 128 + lc + 1];
                }
            }
        }
    }
    if (MODE == 2){
        #pragma unroll
        for (int q = 0; q < 4; q++)
            #pragma unroll
            for (int d = 0; d < 3; d++){
                float v = p3[q][d];
                v += __shfl_xor_sync(0xFFFFFFFFu, v, 1);
                v += __shfl_xor_sync(0xFFFFFFFFu, v, 2);
                p3[q][d] = v;
            }
        if (tt == 0){
            int slot = blockIdx.x * 2 + wn;     // 8 race-free slots per row
            int rb = rowBase + wm * 32 + gg;
            #pragma unroll
            for (int q = 0; q < 4; q++){
                int row = rb + (q & 1) * 8 + (q >> 1) * 16;
                #pragma unroll
                for (int d = 0; d < 3; d++)
                    g_dir8[(size_t)row * 24 + slot * 3 + d] = p3[q][d] * 0.01f;
            }
        }
    }
}

// ================= cumsum: warp per strand, shfl inclusive scan =================
__global__ void cumsum_kernel(float* __restrict__ out, const float* __restrict__ bd)
{
    int gw = (blockIdx.x * blockDim.x + threadIdx.x) >> 5;   // strand
    int lane = threadIdx.x & 31;
    if (gw >= NS) return;
    int s = gw;
    float bias0 = bd[0] * 0.01f, bias1 = bd[1] * 0.01f, bias2 = bd[2] * 0.01f;
    if (lane < 3) out[(size_t)s * 300 + lane] = 0.f;
    float c0 = 0.f, c1 = 0.f, c2 = 0.f;
    #pragma unroll
    for (int ch = 0; ch < 4; ch++){
        int p = ch * 32 + lane;
        float v0 = 0.f, v1 = 0.f, v2 = 0.f;
        if (p < NV){
            const float* b = &g_dir8[(size_t)(s * NV + p) * 24];
            #pragma unroll
            for (int j = 0; j < 8; j++){
                v0 += b[j * 3 + 0];
                v1 += b[j * 3 + 1];
                v2 += b[j * 3 + 2];
            }
            v0 += bias0; v1 += bias1; v2 += bias2;
        }
        #pragma unroll
        for (int o = 1; o < 32; o <<= 1){
            float t0 = __shfl_up_sync(0xFFFFFFFFu, v0, o);
            float t1 = __shfl_up_sync(0xFFFFFFFFu, v1, o);
            float t2 = __shfl_up_sync(0xFFFFFFFFu, v2, o);
            if (lane >= o){ v0 += t0; v1 += t1; v2 += t2; }
        }
        v0 += c0; v1 += c1; v2 += c2;
        if (p < NV){
            float* ob = out + (size_t)s * 300 + (size_t)(p + 1) * 3;
            ob[0] = v0; ob[1] = v1; ob[2] = v2;
        }
        c0 = __shfl_sync(0xFFFFFFFFu, v0, 31);
        c1 = __shfl_sync(0xFFFFFFFFu, v1, 31);
        c2 = __shfl_sync(0xFFFFFFFFu, v2, 31);
    }
}

// ================= host launch =================
static void* sym(const void* s) { void* p = nullptr; cudaGetSymbolAddress(&p, s); return p; }

extern "C" void kernel_launch(void* const* d_in, const int* in_sizes, int n_in,
                              void* d_out, int out_size)
{
    const float* X   = (const float*)d_in[0];
    const float* mv0 = (const float*)d_in[1];  const float* mg0 = (const float*)d_in[2];  const float* mb0 = (const float*)d_in[3];
    const float* mv1 = (const float*)d_in[4];  const float* mg1 = (const float*)d_in[5];  const float* mb1 = (const float*)d_in[6];
    const float* mv2 = (const float*)d_in[7];  const float* mg2 = (const float*)d_in[8];  const float* mb2 = (const float*)d_in[9];
    const float* sv0 = (const float*)d_in[10]; const float* sg0 = (const float*)d_in[11]; const float* sb0 = (const float*)d_in[12];
    const float* sv1 = (const float*)d_in[13]; const float* sg1 = (const float*)d_in[14]; const float* sb1 = (const float*)d_in[15];
    const float* sv2 = (const float*)d_in[16]; const float* sg2 = (const float*)d_in[17]; const float* sb2 = (const float*)d_in[18];
    const float* dv  = (const float*)d_in[19]; const float* dg  = (const float*)d_in[20]; const float* db  = (const float*)d_in[21];
    float* out = (float*)d_out;

    __half* hW1 = (__half*)sym(g_hW1);
    __half* hW2 = (__half*)sym(g_hW2);
    __half* gc0 = (__half*)sym(g_gc0);
    float*  M1  = (float*)sym(g_M1);
    float*  M2  = (float*)sym(g_M2);
    float*  Z0  = (float*)sym(g_Z0);
    float*  Z1  = (float*)sym(g_Z1);
    __half* hHB = (__half*)sym(g_hHB);

    const int mod_smem = MOD_STAGES * 2 * BMM * SST * 4;     // 73728
    const int tc_smem  = TC_STAGES * 32768 + 2048 + 1024;    // 101376
    static int attr_done = 0;
    static cudaStream_t s2 = nullptr;
    static cudaEvent_t evF = nullptr, evZ = nullptr, evR = nullptr,
                       evM1 = nullptr, evM2 = nullptr, evG1a = nullptr, evG2a = nullptr;
    if (!attr_done) {
        cudaFuncSetAttribute(gemm_mod_kernel, cudaFuncAttributeMaxDynamicSharedMemorySize, mod_smem);
        cudaFuncSetAttribute(tc_fp16_kernel<1>, cudaFuncAttributeMaxDynamicSharedMemorySize, tc_smem);
        cudaFuncSetAttribute(tc_fp16_kernel<2>, cudaFuncAttributeMaxDynamicSharedMemorySize, tc_smem);
        cudaStreamCreateWithFlags(&s2, cudaStreamNonBlocking);
        cudaEventCreateWithFlags(&evF,   cudaEventDisableTiming);
        cudaEventCreateWithFlags(&evZ,   cudaEventDisableTiming);
        cudaEventCreateWithFlags(&evR,   cudaEventDisableTiming);
        cudaEventCreateWithFlags(&evM1,  cudaEventDisableTiming);
        cudaEventCreateWithFlags(&evM2,  cudaEventDisableTiming);
        cudaEventCreateWithFlags(&evG1a, cudaEventDisableTiming);
        cudaEventCreateWithFlags(&evG2a, cudaEventDisableTiming);
        attr_done = 1;
    }

    // ---- capture fork: s2 must first wait on an event from stream 0 ----
    cudaEventRecord(evF, 0);
    cudaStreamWaitEvent(s2, evF, 0);

    // s2: Z prefix fill (needed by mod1), then siren prep (needed by GEMM1)
    zfill_kernel<<<256, 256, 0, s2>>>(X);
    cudaEventRecord(evZ, s2);
    prep_rest_kernel<<<1124, 256, 0, s2>>>(sv1, sg1, sv2, sg2, dv, dg, sv0, sg0, sb0);
    cudaEventRecord(evR, s2);

    // stream 0: mod chain with fused weight-norm (raw v weights)
    {
        dim3 grid(512 / BNM, NS / BMM);     // (8, 16) = 128 CTAs
        // mod0: writes gc0 (half complement, for GEMM1 A-produce) + Z0 tail
        gemm_mod_kernel<<<grid, 256, mod_smem>>>(X, mv0, mg0, mb0, nullptr, Z0, gc0, INCH);
        cudaStreamWaitEvent(0, evZ, 0);
        gemm_mod_kernel<<<grid, 256, mod_smem>>>(Z0, mv1, mg1, mb1, M1, Z1, nullptr, KCAT);
        cudaEventRecord(evM1, 0);
        // mod2 on s2 (after prep_rest there; waits mod1)
        cudaStreamWaitEvent(s2, evM1, 0);
        gemm_mod_kernel<<<grid, 256, mod_smem, s2>>>(Z1, mv2, mg2, mb2, M2, nullptr, nullptr, KCAT);
        cudaEventRecord(evM2, s2);
    }

    // big GEMMs, row-chunked for cross-kernel overlap
    cudaStreamWaitEvent(0, evR, 0);
    {
        const int HALF_BLKS = (ROWS / 128) / 2;     // 396
        dim3 gridH(4, HALF_BLKS);
        // GEMM1 first half, then second half (stream 0)
        tc_fp16_kernel<1><<<gridH, 256, tc_smem>>>(nullptr, hW1, sb1, M1, hHB, 0);
        cudaEventRecord(evG1a, 0);
        tc_fp16_kernel<1><<<gridH, 256, tc_smem>>>(nullptr, hW1, sb1, M1, hHB, ROWS / 2);
        // GEMM2 first half on s2, overlapping GEMM1 second half
        cudaStreamWaitEvent(s2, evG1a, 0);
        tc_fp16_kernel<2><<<gridH, 256, tc_smem, s2>>>(hHB, hW2, sb2, M2, nullptr, 0);
        cudaEventRecord(evG2a, s2);
        // GEMM2 second half on stream 0 (needs M2)
        cudaStreamWaitEvent(0, evM2, 0);
        tc_fp16_kernel<2><<<gridH, 256, tc_smem>>>(hHB, hW2, sb2, M2, nullptr, ROWS / 2);
    }

    // cumsum joins both GEMM2 halves
    cudaStreamWaitEvent(0, evG2a, 0);
    cumsum_kernel<<<(NS * 32 + 255) / 256, 256>>>(out, db);
    (void)in_sizes; (void)n_in; (void)out_size;
}